// round 4
// baseline (speedup 1.0000x reference)
#include <cuda_runtime.h>
#include <cstdint>
#include <cstddef>

// ---------------------------------------------------------------------------
// Problem constants
// ---------------------------------------------------------------------------
#define JAX_PARTITIONABLE 1   // modern JAX default (threefry_partitionable=True)

constexpr int ND  = 10000;    // N_DRUGS
constexpr int E   = 1000000;
constexpr int DIM = 64;
constexpr int S   = 16;       // SAMPLE_SIZE
constexpr int CAP = 512;      // per-node bucket capacity (max deg ~160 here)

// ---------------------------------------------------------------------------
// Static device scratch (no runtime allocation allowed)
// ---------------------------------------------------------------------------
__device__ unsigned long long g_bucket[(size_t)ND * CAP];  // (m<<20)|edge_idx
__device__ int   g_cnt[ND];
__device__ int   g_sel[ND * S];      // ALL 16 slots valid after k_select (-1 if none)
__device__ float g_neigh[ND * DIM];
__device__ float g_y[ND * DIM];
__device__ float g_colsum[DIM];
__device__ float g_colsumsq[DIM];
__device__ float g_w2r[DIM];         // rowsum of W2
__device__ float g_b2sum;

// ---------------------------------------------------------------------------
// Threefry2x32 (bit-exact JAX replica)
// ---------------------------------------------------------------------------
__device__ __forceinline__ uint32_t rotl32(uint32_t v, int r) {
    return (v << r) | (v >> (32 - r));
}

__device__ __forceinline__ void tf2x32(uint32_t k0, uint32_t k1,
                                       uint32_t x0, uint32_t x1,
                                       uint32_t& o0, uint32_t& o1)
{
    uint32_t k2 = k0 ^ k1 ^ 0x1BD11BDAu;
    x0 += k0; x1 += k1;
#define TF_R4(a,b,c,d)                                   \
    x0 += x1; x1 = rotl32(x1,a); x1 ^= x0;               \
    x0 += x1; x1 = rotl32(x1,b); x1 ^= x0;               \
    x0 += x1; x1 = rotl32(x1,c); x1 ^= x0;               \
    x0 += x1; x1 = rotl32(x1,d); x1 ^= x0;
    TF_R4(13,15,26,6);   x0 += k1; x1 += k2 + 1u;
    TF_R4(17,29,16,24);  x0 += k2; x1 += k0 + 2u;
    TF_R4(13,15,26,6);   x0 += k0; x1 += k1 + 3u;
    TF_R4(17,29,16,24);  x0 += k1; x1 += k2 + 4u;
    TF_R4(13,15,26,6);   x0 += k2; x1 += k0 + 5u;
#undef TF_R4
    o0 = x0; o1 = x1;
}

__device__ __forceinline__ void derive_k1(uint32_t& a, uint32_t& b) {
#if JAX_PARTITIONABLE
    tf2x32(0u, 42u, 0u, 0u, a, b);
#else
    uint32_t a0,b0,a1,b1;
    tf2x32(0u, 42u, 0u, 2u, a0, b0);
    tf2x32(0u, 42u, 1u, 3u, a1, b1);
    a = a0; b = a1;
#endif
}

__device__ __forceinline__ void derive_k2(uint32_t& a, uint32_t& b) {
#if JAX_PARTITIONABLE
    tf2x32(0u, 42u, 0u, 1u, a, b);
#else
    uint32_t a0,b0,a1,b1;
    tf2x32(0u, 42u, 0u, 2u, a0, b0);
    tf2x32(0u, 42u, 1u, 3u, a1, b1);
    a = b0; b = b1;
#endif
}

__device__ __forceinline__ uint32_t jax_bits32(uint32_t ka, uint32_t kb,
                                               uint32_t i, uint32_t n)
{
#if JAX_PARTITIONABLE
    uint32_t o0, o1;
    tf2x32(ka, kb, 0u, i, o0, o1);
    return o0 ^ o1;
#else
    uint32_t half = n >> 1;
    uint32_t j = (i < half) ? i : (i - half);
    uint32_t o0, o1;
    tf2x32(ka, kb, j, j + half, o0, o1);
    return (i < half) ? o0 : o1;
#endif
}

// ---------------------------------------------------------------------------
// Packed fp32x2 helpers (FFMA2 path — only reachable via PTX)
// ---------------------------------------------------------------------------
__device__ __forceinline__ void fma2(unsigned long long& acc,
                                     unsigned long long a,
                                     unsigned long long b)
{
    asm("fma.rn.f32x2 %0, %1, %2, %0;" : "+l"(acc) : "l"(a), "l"(b));
}
__device__ __forceinline__ unsigned long long pack2(float lo, float hi)
{
    union { unsigned long long u; float2 f; } cv;
    cv.f = make_float2(lo, hi);
    return cv.u;
}
__device__ __forceinline__ float2 unpack2(unsigned long long u)
{
    union { unsigned long long u; float2 f; } cv;
    cv.u = u;
    return cv.f;
}

// ---------------------------------------------------------------------------
// K0: zero counters, precompute w2 rowsums / b2 sum
// ---------------------------------------------------------------------------
__global__ void k_init(const float* __restrict__ W2, const float* __restrict__ b2)
{
    int t = blockIdx.x * blockDim.x + threadIdx.x;
    if (t < ND) g_cnt[t] = 0;
    if (t < DIM) {
        g_colsum[t]   = 0.f;
        g_colsumsq[t] = 0.f;
        float s = 0.f;
        #pragma unroll 8
        for (int k = 0; k < DIM; k++) s += W2[t * DIM + k];
        g_w2r[t] = s;
    }
    if (t == 0) {
        float s = 0.f;
        #pragma unroll 8
        for (int k = 0; k < DIM; k++) s += b2[k];
        g_b2sum = s;
    }
}

// ---------------------------------------------------------------------------
// K1: per-edge uniform r, scatter (m<<20 | edge_idx) into per-node buckets
// ---------------------------------------------------------------------------
__global__ void k_scatter(const int* __restrict__ DKG)
{
    int i = blockIdx.x * blockDim.x + threadIdx.x;
    if (i >= E) return;
    uint32_t ka, kb;
    derive_k1(ka, kb);
    uint32_t bits = jax_bits32(ka, kb, (uint32_t)i, (uint32_t)E);
    uint32_t m = bits >> 9;                   // r = m * 2^-23 exactly
    int head = DKG[3 * i];
    int c = atomicAdd(&g_cnt[head], 1);
    if (c < CAP)
        g_bucket[(size_t)head * CAP + c] =
            (((unsigned long long)m) << 20) | (unsigned long long)(uint32_t)i;
}

// ---------------------------------------------------------------------------
// K2: per-node exact rank-by-count; fill ALL 16 slots of g_sel
// ---------------------------------------------------------------------------
__global__ __launch_bounds__(128) void k_select()
{
    __shared__ unsigned long long sk[CAP];
    __shared__ int ssel[S];
    int d = blockIdx.x;
    int deg = g_cnt[d];
    if (deg > CAP) deg = CAP;
    if (threadIdx.x < S) ssel[threadIdx.x] = -1;
    for (int i = threadIdx.x; i < deg; i += blockDim.x)
        sk[i] = g_bucket[(size_t)d * CAP + i];
    __syncthreads();
    for (int i = threadIdx.x; i < deg; i += blockDim.x) {
        unsigned long long key = sk[i];
        int r = 0;
        for (int j = 0; j < deg; j++) r += (sk[j] < key);   // keys unique
        if (r < S) ssel[r] = (int)(key & 0xFFFFFull);
    }
    __syncthreads();
    if (threadIdx.x < S) {
        int nsel = (deg < S) ? deg : S;
        int e = ssel[threadIdx.x];
        if ((int)threadIdx.x >= nsel && deg > 0) {
            // deg < S: extra draws WITH replacement (statistically dead here)
            int t = threadIdx.x - nsel;
            uint32_t ka, kb; derive_k2(ka, kb);
            uint32_t idx = (uint32_t)(d * S + t);
            uint32_t hi = jax_bits32(ka, kb, idx,          2u * ND * S);
            uint32_t lo = jax_bits32(ka, kb, idx + ND * S, 2u * ND * S);
            const uint32_t span = 2147483647u;
            uint32_t mult = (65536u * 65536u) % span;
            uint32_t off  = ((hi % span) * mult + (lo % span)) % span;
            e = ssel[(int)(off % (uint32_t)deg)];   // rank < deg < S, all kept
        }
        g_sel[d * S + threadIdx.x] = e;
    }
}

// ---------------------------------------------------------------------------
// K3: 4 nodes / block, 64 edges / block. Packed fp32x2 MLP + aggregation.
//   Per warp: 8 edges. Per thread: 4 edges (eg half) x 4 cols (g group).
//   score(e) = sigmoid(h0 @ W1 + b1) . w2row + sum(b2)
//   neigh[d] = sum_e score(e) * tail_emb[tail_e]
// ---------------------------------------------------------------------------
__global__ __launch_bounds__(256) void k_node2(
    const int*   __restrict__ DKG,
    const float* __restrict__ drug,
    const float* __restrict__ rel_emb,
    const float* __restrict__ tail_emb,
    const float* __restrict__ W1,
    const float* __restrict__ b1)
{
    extern __shared__ float sm[];
    float2* H2    = (float2*)sm;           // [64 edges][64 j], duplicated (h,h): 32 KB
    float*  W1s   = sm + 8192;             // [j][c] 4096 floats: 16 KB
    float*  de    = W1s + 4096;            // [4 nodes][64]
    float*  pacc  = de + 256;              // [8 warps][64]
    float*  b1s   = pacc + 512;            // 64
    float*  w2s   = b1s + 64;              // 64
    int*    elist = (int*)(w2s + 64);      // 64
    int*    tlist = elist + 64;            // 64
    int*    rlist = tlist + 64;            // 64

    int tid  = threadIdx.x;
    int lane = tid & 31, w = tid >> 5;
    int g    = lane & 15, eg = lane >> 4;
    int d0   = blockIdx.x * 4;

    for (int i = tid; i < 1024; i += 256)
        ((float4*)W1s)[i] = ((const float4*)W1)[i];
    if (tid < 64) { b1s[tid] = b1[tid]; w2s[tid] = g_w2r[tid]; }
    de[tid] = drug[(d0 + (tid >> 6)) * DIM + (tid & 63)];
    if (tid < 64) {
        int e = g_sel[(d0 + (tid >> 4)) * S + (tid & 15)];
        elist[tid] = e;
        int ee = (e < 0) ? 0 : e;
        tlist[tid] = DKG[3 * ee + 1];
        rlist[tid] = DKG[3 * ee + 2];
    }
    __syncthreads();

    // H2 fill: 4 threads per edge, each covers 16 j values
    {
        int le = tid >> 2;                 // block-local edge 0..63
        int j0 = (tid & 3) * 16;
        int n  = le >> 4;
        const float4* rr = (const float4*)(rel_emb + (size_t)rlist[le] * DIM);
        const float*  dn = de + n * 64;
        #pragma unroll
        for (int jj = 0; jj < 16; jj += 4) {
            float4 rv = rr[(j0 + jj) >> 2];
            float h0 = dn[j0+jj+0] * rv.x;
            float h1 = dn[j0+jj+1] * rv.y;
            float h2v= dn[j0+jj+2] * rv.z;
            float h3 = dn[j0+jj+3] * rv.w;
            H2[le * 64 + j0 + jj + 0] = make_float2(h0, h0);
            H2[le * 64 + j0 + jj + 1] = make_float2(h1, h1);
            H2[le * 64 + j0 + jj + 2] = make_float2(h2v, h2v);
            H2[le * 64 + j0 + jj + 3] = make_float2(h3, h3);
        }
    }
    __syncthreads();

    // main GEMM: thread covers cols c0..c0+3 for 4 edges
    int n      = w >> 1;
    int lebase = n * 16 + (w & 1) * 8 + eg * 4;
    int c0     = g * 4;

    unsigned long long accA[4], accB[4];
    {
        unsigned long long bA = pack2(b1s[c0],     b1s[c0 + 1]);
        unsigned long long bB = pack2(b1s[c0 + 2], b1s[c0 + 3]);
        #pragma unroll
        for (int q = 0; q < 4; q++) { accA[q] = bA; accB[q] = bB; }
    }

    const float2* h0p = H2 + lebase * 64;
    #pragma unroll 8
    for (int j = 0; j < 64; j += 2) {
        ulonglong2 w0 = *(const ulonglong2*)(W1s + j * 64 + c0);
        ulonglong2 w1 = *(const ulonglong2*)(W1s + (j + 1) * 64 + c0);
        #pragma unroll
        for (int q = 0; q < 4; q++) {
            ulonglong2 hv = *(const ulonglong2*)(h0p + q * 64 + j);
            fma2(accA[q], hv.x, w0.x);
            fma2(accB[q], hv.x, w0.y);
            fma2(accA[q], hv.y, w1.x);
            fma2(accB[q], hv.y, w1.y);
        }
    }

    // epilogue: sigmoid . w2row, reduce over 64 cols, accumulate tail rows
    float b2s = g_b2sum;
    float4 w2v = *(const float4*)(w2s + c0);
    float4 p = make_float4(0.f, 0.f, 0.f, 0.f);
    #pragma unroll
    for (int q = 0; q < 4; q++) {
        float2 yA = unpack2(accA[q]);
        float2 yB = unpack2(accB[q]);
        float v = w2v.x / (1.f + __expf(-yA.x))
                + w2v.y / (1.f + __expf(-yA.y))
                + w2v.z / (1.f + __expf(-yB.x))
                + w2v.w / (1.f + __expf(-yB.y));
        #pragma unroll
        for (int o = 8; o; o >>= 1) v += __shfl_xor_sync(0xFFFFFFFFu, v, o);
        int le = lebase + q;
        if (elist[le] >= 0) {
            float score = v + b2s;
            float4 tv = *(const float4*)(tail_emb + (size_t)tlist[le] * DIM + c0);
            p.x += score * tv.x; p.y += score * tv.y;
            p.z += score * tv.z; p.w += score * tv.w;
        }
    }
    p.x += __shfl_xor_sync(0xFFFFFFFFu, p.x, 16);
    p.y += __shfl_xor_sync(0xFFFFFFFFu, p.y, 16);
    p.z += __shfl_xor_sync(0xFFFFFFFFu, p.z, 16);
    p.w += __shfl_xor_sync(0xFFFFFFFFu, p.w, 16);
    if (eg == 0) *(float4*)(pacc + w * 64 + c0) = p;
    __syncthreads();

    {
        int n2 = tid >> 6, c = tid & 63;
        g_neigh[(d0 + n2) * DIM + c] =
            pacc[(2 * n2) * 64 + c] + pacc[(2 * n2 + 1) * 64 + c];
    }
}

// ---------------------------------------------------------------------------
// K4: y = [drug | neigh] @ Wc + bc, plus column sum / sumsq partials
// ---------------------------------------------------------------------------
__global__ __launch_bounds__(256) void k_gemm(
    const float* __restrict__ drug,
    const float* __restrict__ Wc,
    const float* __restrict__ bc)
{
    __shared__ float Wcs[2 * DIM * DIM];      // 32 KB
    __shared__ float rsum[4][DIM], rsq[4][DIM];
    int tid = threadIdx.x;
    int k   = tid & 63;
    int ty  = tid >> 6;
    for (int i = tid; i < 2 * DIM * DIM; i += 256) Wcs[i] = Wc[i];
    __syncthreads();

    float ls = 0.f, lq = 0.f;
    int r0 = blockIdx.x * 16;
    for (int it = 0; it < 4; it++) {
        int r = r0 + it * 4 + ty;
        if (r < ND) {
            float acc = bc[k];
            #pragma unroll 8
            for (int j = 0; j < DIM; j++) acc += drug[r * DIM + j] * Wcs[j * DIM + k];
            #pragma unroll 8
            for (int j = 0; j < DIM; j++) acc += g_neigh[r * DIM + j] * Wcs[(DIM + j) * DIM + k];
            g_y[r * DIM + k] = acc;
            ls += acc; lq += acc * acc;
        }
    }
    rsum[ty][k] = ls; rsq[ty][k] = lq;
    __syncthreads();
    if (ty == 0) {
        float s = rsum[0][k] + rsum[1][k] + rsum[2][k] + rsum[3][k];
        float q = rsq[0][k]  + rsq[1][k]  + rsq[2][k]  + rsq[3][k];
        atomicAdd(&g_colsum[k],   s);
        atomicAdd(&g_colsumsq[k], q);
    }
}

// ---------------------------------------------------------------------------
// K5: batchnorm + output (stats recomputed per thread — trivially cheap)
// ---------------------------------------------------------------------------
__global__ void k_out(const float* __restrict__ gamma,
                      const float* __restrict__ beta,
                      float* __restrict__ out)
{
    int i = blockIdx.x * blockDim.x + threadIdx.x;
    if (i < ND * DIM) {
        int k = i & 63;
        float mean = g_colsum[k] * (1.f / ND);
        float var  = g_colsumsq[k] * (1.f / ND) - mean * mean;
        out[i] = gamma[k] * (g_y[i] - mean) * rsqrtf(var + 1e-5f) + beta[k];
    }
}

// ---------------------------------------------------------------------------
// Entry point. Output tuple: [HFEmbeding (10000x64) | out (10000x64) | X (10000)]
// ---------------------------------------------------------------------------
extern "C" void kernel_launch(void* const* d_in, const int* in_sizes, int n_in,
                              void* d_out, int out_size)
{
    const float* HF    = (const float*)d_in[0];
    const float* X     = (const float*)d_in[1];
    const float* drug  = (const float*)d_in[2];
    const float* rel   = (const float*)d_in[3];
    const float* tail  = (const float*)d_in[4];
    const float* W1    = (const float*)d_in[5];
    const float* b1    = (const float*)d_in[6];
    const float* W2    = (const float*)d_in[7];
    const float* b2    = (const float*)d_in[8];
    const float* Wc    = (const float*)d_in[9];
    const float* bc    = (const float*)d_in[10];
    const float* gamma = (const float*)d_in[11];
    const float* beta  = (const float*)d_in[12];
    const int*   DKG   = (const int*)d_in[13];
    float* out = (float*)d_out;

    const int node_smem = (8192 * 2 + 4096 + 256 + 512 + 64 + 64) * 4 + 3 * 64 * 4;
    cudaFuncSetAttribute(k_node2, cudaFuncAttributeMaxDynamicSharedMemorySize,
                         node_smem);   // idempotent; set on the (uncaptured) first call

    k_init   <<<(ND + 255) / 256, 256>>>(W2, b2);
    k_scatter<<<(E + 255) / 256, 256>>>(DKG);
    k_select <<<ND, 128>>>();
    k_node2  <<<ND / 4, 256, node_smem>>>(DKG, drug, rel, tail, W1, b1);
    k_gemm   <<<(ND + 15) / 16, 256>>>(drug, Wc, bc);
    k_out    <<<(ND * DIM + 255) / 256, 256>>>(gamma, beta, out + ND * DIM);

    cudaMemcpyAsync(out,                HF, (size_t)ND * DIM * sizeof(float),
                    cudaMemcpyDeviceToDevice);
    cudaMemcpyAsync(out + 2 * ND * DIM, X,  (size_t)ND * sizeof(float),
                    cudaMemcpyDeviceToDevice);
}

// round 7
// speedup vs baseline: 1.1857x; 1.1857x over previous
#include <cuda_runtime.h>
#include <cstdint>
#include <cstddef>

// ---------------------------------------------------------------------------
// Problem constants
// ---------------------------------------------------------------------------
#define JAX_PARTITIONABLE 1   // modern JAX default (threefry_partitionable=True)

constexpr int ND  = 10000;    // N_DRUGS
constexpr int E   = 1000000;
constexpr int DIM = 64;
constexpr int S   = 16;       // SAMPLE_SIZE
constexpr int CAP = 512;      // per-node bucket capacity (max deg ~160 here)

// ---------------------------------------------------------------------------
// Static device scratch (no runtime allocation allowed)
// ---------------------------------------------------------------------------
__device__ unsigned long long g_bucket[(size_t)ND * CAP];  // (m<<20)|edge_idx
__device__ int   g_cnt[ND];
__device__ int   g_sel[ND * S];      // ALL 16 slots valid after k_select (-1 if none)
__device__ float g_neigh[ND * DIM];
__device__ float g_y[ND * DIM];
__device__ float g_colsum[DIM];
__device__ float g_colsumsq[DIM];
__device__ float g_w2r[DIM];         // rowsum of W2
__device__ float g_b2sum;

// ---------------------------------------------------------------------------
// Threefry2x32 (bit-exact JAX replica)
// ---------------------------------------------------------------------------
__device__ __forceinline__ uint32_t rotl32(uint32_t v, int r) {
    return (v << r) | (v >> (32 - r));
}

__device__ __forceinline__ void tf2x32(uint32_t k0, uint32_t k1,
                                       uint32_t x0, uint32_t x1,
                                       uint32_t& o0, uint32_t& o1)
{
    uint32_t k2 = k0 ^ k1 ^ 0x1BD11BDAu;
    x0 += k0; x1 += k1;
#define TF_R4(a,b,c,d)                                   \
    x0 += x1; x1 = rotl32(x1,a); x1 ^= x0;               \
    x0 += x1; x1 = rotl32(x1,b); x1 ^= x0;               \
    x0 += x1; x1 = rotl32(x1,c); x1 ^= x0;               \
    x0 += x1; x1 = rotl32(x1,d); x1 ^= x0;
    TF_R4(13,15,26,6);   x0 += k1; x1 += k2 + 1u;
    TF_R4(17,29,16,24);  x0 += k2; x1 += k0 + 2u;
    TF_R4(13,15,26,6);   x0 += k0; x1 += k1 + 3u;
    TF_R4(17,29,16,24);  x0 += k1; x1 += k2 + 4u;
    TF_R4(13,15,26,6);   x0 += k2; x1 += k0 + 5u;
#undef TF_R4
    o0 = x0; o1 = x1;
}

__device__ __forceinline__ void derive_k1(uint32_t& a, uint32_t& b) {
#if JAX_PARTITIONABLE
    tf2x32(0u, 42u, 0u, 0u, a, b);
#else
    uint32_t a0,b0,a1,b1;
    tf2x32(0u, 42u, 0u, 2u, a0, b0);
    tf2x32(0u, 42u, 1u, 3u, a1, b1);
    a = a0; b = a1;
#endif
}

__device__ __forceinline__ void derive_k2(uint32_t& a, uint32_t& b) {
#if JAX_PARTITIONABLE
    tf2x32(0u, 42u, 0u, 1u, a, b);
#else
    uint32_t a0,b0,a1,b1;
    tf2x32(0u, 42u, 0u, 2u, a0, b0);
    tf2x32(0u, 42u, 1u, 3u, a1, b1);
    a = b0; b = b1;
#endif
}

__device__ __forceinline__ uint32_t jax_bits32(uint32_t ka, uint32_t kb,
                                               uint32_t i, uint32_t n)
{
#if JAX_PARTITIONABLE
    uint32_t o0, o1;
    tf2x32(ka, kb, 0u, i, o0, o1);
    return o0 ^ o1;
#else
    uint32_t half = n >> 1;
    uint32_t j = (i < half) ? i : (i - half);
    uint32_t o0, o1;
    tf2x32(ka, kb, j, j + half, o0, o1);
    return (i < half) ? o0 : o1;
#endif
}

// ---------------------------------------------------------------------------
// Packed fp32x2 helpers (FFMA2 path — only reachable via PTX)
// ---------------------------------------------------------------------------
__device__ __forceinline__ void fma2(unsigned long long& acc,
                                     unsigned long long a,
                                     unsigned long long b)
{
    asm("fma.rn.f32x2 %0, %1, %2, %0;" : "+l"(acc) : "l"(a), "l"(b));
}
__device__ __forceinline__ unsigned long long pack2(float lo, float hi)
{
    union { unsigned long long u; float2 f; } cv;
    cv.f = make_float2(lo, hi);
    return cv.u;
}
__device__ __forceinline__ float2 unpack2(unsigned long long u)
{
    union { unsigned long long u; float2 f; } cv;
    cv.u = u;
    return cv.f;
}

// ---------------------------------------------------------------------------
// K0: zero counters, precompute w2 rowsums / b2 sum
// ---------------------------------------------------------------------------
__global__ void k_init(const float* __restrict__ W2, const float* __restrict__ b2)
{
    int t = blockIdx.x * blockDim.x + threadIdx.x;
    if (t < ND) g_cnt[t] = 0;
    if (t < DIM) {
        g_colsum[t]   = 0.f;
        g_colsumsq[t] = 0.f;
        float s = 0.f;
        #pragma unroll 8
        for (int k = 0; k < DIM; k++) s += W2[t * DIM + k];
        g_w2r[t] = s;
    }
    if (t == 0) {
        float s = 0.f;
        #pragma unroll 8
        for (int k = 0; k < DIM; k++) s += b2[k];
        g_b2sum = s;
    }
}

// ---------------------------------------------------------------------------
// K1: per-edge uniform r, scatter (m<<20 | edge_idx) into per-node buckets
// ---------------------------------------------------------------------------
__global__ void k_scatter(const int* __restrict__ DKG)
{
    int i = blockIdx.x * blockDim.x + threadIdx.x;
    if (i >= E) return;
    uint32_t ka, kb;
    derive_k1(ka, kb);
    uint32_t bits = jax_bits32(ka, kb, (uint32_t)i, (uint32_t)E);
    uint32_t m = bits >> 9;                   // r = m * 2^-23 exactly
    int head = DKG[3 * i];
    int c = atomicAdd(&g_cnt[head], 1);
    if (c < CAP)
        g_bucket[(size_t)head * CAP + c] =
            (((unsigned long long)m) << 20) | (unsigned long long)(uint32_t)i;
}

// ---------------------------------------------------------------------------
// K2: per-node exact rank-by-count; fill ALL 16 slots of g_sel
// ---------------------------------------------------------------------------
__global__ __launch_bounds__(128) void k_select()
{
    __shared__ unsigned long long sk[CAP];
    __shared__ int ssel[S];
    int d = blockIdx.x;
    int deg = g_cnt[d];
    if (deg > CAP) deg = CAP;
    if (threadIdx.x < S) ssel[threadIdx.x] = -1;
    for (int i = threadIdx.x; i < deg; i += blockDim.x)
        sk[i] = g_bucket[(size_t)d * CAP + i];
    __syncthreads();
    for (int i = threadIdx.x; i < deg; i += blockDim.x) {
        unsigned long long key = sk[i];
        int r = 0;
        for (int j = 0; j < deg; j++) r += (sk[j] < key);   // keys unique
        if (r < S) ssel[r] = (int)(key & 0xFFFFFull);
    }
    __syncthreads();
    if (threadIdx.x < S) {
        int nsel = (deg < S) ? deg : S;
        int e = ssel[threadIdx.x];
        if ((int)threadIdx.x >= nsel && deg > 0) {
            // deg < S: extra draws WITH replacement (statistically dead here)
            int t = threadIdx.x - nsel;
            uint32_t ka, kb; derive_k2(ka, kb);
            uint32_t idx = (uint32_t)(d * S + t);
            uint32_t hi = jax_bits32(ka, kb, idx,          2u * ND * S);
            uint32_t lo = jax_bits32(ka, kb, idx + ND * S, 2u * ND * S);
            const uint32_t span = 2147483647u;
            uint32_t mult = (65536u * 65536u) % span;
            uint32_t off  = ((hi % span) * mult + (lo % span)) % span;
            e = ssel[(int)(off % (uint32_t)deg)];   // rank < deg < S, all kept
        }
        g_sel[d * S + threadIdx.x] = e;
    }
}

// ---------------------------------------------------------------------------
// K3: 4 nodes / block, 64 edges / block. Packed fp32x2 MLP + aggregation.
//   H stored TRANSPOSED [j][edge] as duplicated (h,h) float2 -> per-j loads are
//   one LDS.128 per 2 edges with full warp broadcast dedup; W natural [j][c].
//   Per warp per j: 4 smem wavefront-cycles vs 8 FFMA2 -> FMA2-pipe-balanced.
// ---------------------------------------------------------------------------
__global__ __launch_bounds__(256) void k_node3(
    const int*   __restrict__ DKG,
    const float* __restrict__ drug,
    const float* __restrict__ rel_emb,
    const float* __restrict__ tail_emb,
    const float* __restrict__ W1,
    const float* __restrict__ b1)
{
    extern __shared__ float sm[];
    float2* H2    = (float2*)sm;           // [64 j][64 edges] dup (h,h): 32 KB
    float*  W1s   = sm + 8192;             // [j][c]: 16 KB
    float*  de    = W1s + 4096;            // [4 nodes][64]
    float*  pacc  = de + 256;              // [8 warps][64]
    float*  b1s   = pacc + 512;            // 64
    float*  w2s   = b1s + 64;              // 64
    int*    elist = (int*)(w2s + 64);      // 64
    int*    tlist = elist + 64;            // 64
    int*    rlist = tlist + 64;            // 64

    int tid  = threadIdx.x;
    int lane = tid & 31, w = tid >> 5;
    int g    = lane & 15, eg = lane >> 4;
    int d0   = blockIdx.x * 4;

    for (int i = tid; i < 1024; i += 256)
        ((float4*)W1s)[i] = ((const float4*)W1)[i];
    if (tid < 64) { b1s[tid] = b1[tid]; w2s[tid] = g_w2r[tid]; }
    de[tid] = drug[(d0 + (tid >> 6)) * DIM + (tid & 63)];
    if (tid < 64) {
        int e = g_sel[(d0 + (tid >> 4)) * S + (tid & 15)];
        elist[tid] = e;
        int ee = (e < 0) ? 0 : e;
        tlist[tid] = DKG[3 * ee + 1];
        rlist[tid] = DKG[3 * ee + 2];
    }
    __syncthreads();

    // H fill (transposed): thread -> edge le, j-chunk of 16
    {
        int le = tid & 63;
        int j0 = (tid >> 6) * 16;
        int n  = le >> 4;
        const float4* rr = (const float4*)(rel_emb + (size_t)rlist[le] * DIM);
        const float*  dn = de + n * 64;
        #pragma unroll
        for (int jj = 0; jj < 16; jj += 4) {
            float4 rv = rr[(j0 + jj) >> 2];
            float4 dv = *(const float4*)(dn + j0 + jj);
            float h0 = dv.x * rv.x;
            float h1 = dv.y * rv.y;
            float h2 = dv.z * rv.z;
            float h3 = dv.w * rv.w;
            H2[(j0 + jj + 0) * 64 + le] = make_float2(h0, h0);
            H2[(j0 + jj + 1) * 64 + le] = make_float2(h1, h1);
            H2[(j0 + jj + 2) * 64 + le] = make_float2(h2, h2);
            H2[(j0 + jj + 3) * 64 + le] = make_float2(h3, h3);
        }
    }
    __syncthreads();

    // main GEMM: thread covers cols c0..c0+3 for 4 edges lebase..lebase+3
    int n      = w >> 1;
    int lebase = n * 16 + (w & 1) * 8 + eg * 4;
    int c0     = g * 4;

    unsigned long long accA[4], accB[4];
    {
        unsigned long long bA = pack2(b1s[c0],     b1s[c0 + 1]);
        unsigned long long bB = pack2(b1s[c0 + 2], b1s[c0 + 3]);
        #pragma unroll
        for (int q = 0; q < 4; q++) { accA[q] = bA; accB[q] = bB; }
    }

    #pragma unroll 4
    for (int j = 0; j < 64; j++) {
        ulonglong2 wv = *(const ulonglong2*)(W1s + j * 64 + c0);
        ulonglong2 ha = *(const ulonglong2*)(H2 + j * 64 + lebase);
        ulonglong2 hb = *(const ulonglong2*)(H2 + j * 64 + lebase + 2);
        fma2(accA[0], ha.x, wv.x);  fma2(accB[0], ha.x, wv.y);
        fma2(accA[1], ha.y, wv.x);  fma2(accB[1], ha.y, wv.y);
        fma2(accA[2], hb.x, wv.x);  fma2(accB[2], hb.x, wv.y);
        fma2(accA[3], hb.y, wv.x);  fma2(accB[3], hb.y, wv.y);
    }

    // epilogue: sigmoid . w2row, reduce over 64 cols, accumulate tail rows
    float b2s = g_b2sum;
    float4 w2v = *(const float4*)(w2s + c0);
    float4 p = make_float4(0.f, 0.f, 0.f, 0.f);
    #pragma unroll
    for (int q = 0; q < 4; q++) {
        float2 yA = unpack2(accA[q]);
        float2 yB = unpack2(accB[q]);
        float v = w2v.x / (1.f + __expf(-yA.x))
                + w2v.y / (1.f + __expf(-yA.y))
                + w2v.z / (1.f + __expf(-yB.x))
                + w2v.w / (1.f + __expf(-yB.y));
        #pragma unroll
        for (int o = 8; o; o >>= 1) v += __shfl_xor_sync(0xFFFFFFFFu, v, o);
        int le = lebase + q;
        if (elist[le] >= 0) {
            float score = v + b2s;
            float4 tv = *(const float4*)(tail_emb + (size_t)tlist[le] * DIM + c0);
            p.x += score * tv.x; p.y += score * tv.y;
            p.z += score * tv.z; p.w += score * tv.w;
        }
    }
    p.x += __shfl_xor_sync(0xFFFFFFFFu, p.x, 16);
    p.y += __shfl_xor_sync(0xFFFFFFFFu, p.y, 16);
    p.z += __shfl_xor_sync(0xFFFFFFFFu, p.z, 16);
    p.w += __shfl_xor_sync(0xFFFFFFFFu, p.w, 16);
    if (eg == 0) *(float4*)(pacc + w * 64 + c0) = p;
    __syncthreads();

    {
        int n2 = tid >> 6, c = tid & 63;
        g_neigh[(d0 + n2) * DIM + c] =
            pacc[(2 * n2) * 64 + c] + pacc[(2 * n2 + 1) * 64 + c];
    }
}

// ---------------------------------------------------------------------------
// K4: y = [drug | neigh] @ Wc + bc, plus column sum / sumsq partials
// ---------------------------------------------------------------------------
__global__ __launch_bounds__(256) void k_gemm(
    const float* __restrict__ drug,
    const float* __restrict__ Wc,
    const float* __restrict__ bc)
{
    __shared__ float Wcs[2 * DIM * DIM];      // 32 KB
    __shared__ float rsum[4][DIM], rsq[4][DIM];
    int tid = threadIdx.x;
    int k   = tid & 63;
    int ty  = tid >> 6;
    for (int i = tid; i < 2 * DIM * DIM; i += 256) Wcs[i] = Wc[i];
    __syncthreads();

    float ls = 0.f, lq = 0.f;
    int r0 = blockIdx.x * 16;
    for (int it = 0; it < 4; it++) {
        int r = r0 + it * 4 + ty;
        if (r < ND) {
            float acc = bc[k];
            #pragma unroll 8
            for (int j = 0; j < DIM; j++) acc += drug[r * DIM + j] * Wcs[j * DIM + k];
            #pragma unroll 8
            for (int j = 0; j < DIM; j++) acc += g_neigh[r * DIM + j] * Wcs[(DIM + j) * DIM + k];
            g_y[r * DIM + k] = acc;
            ls += acc; lq += acc * acc;
        }
    }
    rsum[ty][k] = ls; rsq[ty][k] = lq;
    __syncthreads();
    if (ty == 0) {
        float s = rsum[0][k] + rsum[1][k] + rsum[2][k] + rsum[3][k];
        float q = rsq[0][k]  + rsq[1][k]  + rsq[2][k]  + rsq[3][k];
        atomicAdd(&g_colsum[k],   s);
        atomicAdd(&g_colsumsq[k], q);
    }
}

// ---------------------------------------------------------------------------
// K5: batchnorm + output (stats recomputed per thread — trivially cheap)
// ---------------------------------------------------------------------------
__global__ void k_out(const float* __restrict__ gamma,
                      const float* __restrict__ beta,
                      float* __restrict__ out)
{
    int i = blockIdx.x * blockDim.x + threadIdx.x;
    if (i < ND * DIM) {
        int k = i & 63;
        float mean = g_colsum[k] * (1.f / ND);
        float var  = g_colsumsq[k] * (1.f / ND) - mean * mean;
        out[i] = gamma[k] * (g_y[i] - mean) * rsqrtf(var + 1e-5f) + beta[k];
    }
}

// ---------------------------------------------------------------------------
// Entry point. Output tuple: [HFEmbeding (10000x64) | out (10000x64) | X (10000)]
// ---------------------------------------------------------------------------
extern "C" void kernel_launch(void* const* d_in, const int* in_sizes, int n_in,
                              void* d_out, int out_size)
{
    const float* HF    = (const float*)d_in[0];
    const float* X     = (const float*)d_in[1];
    const float* drug  = (const float*)d_in[2];
    const float* rel   = (const float*)d_in[3];
    const float* tail  = (const float*)d_in[4];
    const float* W1    = (const float*)d_in[5];
    const float* b1    = (const float*)d_in[6];
    const float* W2    = (const float*)d_in[7];
    const float* b2    = (const float*)d_in[8];
    const float* Wc    = (const float*)d_in[9];
    const float* bc    = (const float*)d_in[10];
    const float* gamma = (const float*)d_in[11];
    const float* beta  = (const float*)d_in[12];
    const int*   DKG   = (const int*)d_in[13];
    float* out = (float*)d_out;

    // floats: H2 8192 + W1s 4096 + de 256 + pacc 512 + b1s 64 + w2s 64
    // ints:   elist/tlist/rlist 192
    const int node_smem = (8192 + 4096 + 256 + 512 + 64 + 64) * 4 + 3 * 64 * 4;
    cudaFuncSetAttribute(k_node3, cudaFuncAttributeMaxDynamicSharedMemorySize,
                         node_smem);   // idempotent; set on the (uncaptured) first call

    k_init   <<<(ND + 255) / 256, 256>>>(W2, b2);
    k_scatter<<<(E + 255) / 256, 256>>>(DKG);
    k_select <<<ND, 128>>>();
    k_node3  <<<ND / 4, 256, node_smem>>>(DKG, drug, rel, tail, W1, b1);
    k_gemm   <<<(ND + 15) / 16, 256>>>(drug, Wc, bc);
    k_out    <<<(ND * DIM + 255) / 256, 256>>>(gamma, beta, out + ND * DIM);

    cudaMemcpyAsync(out,                HF, (size_t)ND * DIM * sizeof(float),
                    cudaMemcpyDeviceToDevice);
    cudaMemcpyAsync(out + 2 * ND * DIM, X,  (size_t)ND * sizeof(float),
                    cudaMemcpyDeviceToDevice);
}

// round 8
// speedup vs baseline: 1.2586x; 1.0615x over previous
#include <cuda_runtime.h>
#include <cstdint>
#include <cstddef>

// ---------------------------------------------------------------------------
// Problem constants
// ---------------------------------------------------------------------------
#define JAX_PARTITIONABLE 1   // modern JAX default (threefry_partitionable=True)

constexpr int ND  = 10000;    // N_DRUGS
constexpr int E   = 1000000;
constexpr int DIM = 64;
constexpr int S   = 16;       // SAMPLE_SIZE
constexpr int CAP = 512;      // per-node bucket capacity (max deg ~160 here)

// ---------------------------------------------------------------------------
// Static device scratch (no runtime allocation allowed)
// ---------------------------------------------------------------------------
__device__ unsigned long long g_bucket[(size_t)ND * CAP];  // (m<<20)|edge_idx
__device__ int   g_cnt[ND];
__device__ int   g_sel[ND * S];      // ALL 16 slots valid after select (-1 if none)
__device__ float g_neigh[ND * DIM];
__device__ float g_y[ND * DIM];
__device__ float g_colsum[DIM];
__device__ float g_colsumsq[DIM];
__device__ float g_w2r[DIM];         // rowsum of W2
__device__ float g_b2sum;

// ---------------------------------------------------------------------------
// Threefry2x32 (bit-exact JAX replica)
// ---------------------------------------------------------------------------
__device__ __forceinline__ uint32_t rotl32(uint32_t v, int r) {
    return (v << r) | (v >> (32 - r));
}

__device__ __forceinline__ void tf2x32(uint32_t k0, uint32_t k1,
                                       uint32_t x0, uint32_t x1,
                                       uint32_t& o0, uint32_t& o1)
{
    uint32_t k2 = k0 ^ k1 ^ 0x1BD11BDAu;
    x0 += k0; x1 += k1;
#define TF_R4(a,b,c,d)                                   \
    x0 += x1; x1 = rotl32(x1,a); x1 ^= x0;               \
    x0 += x1; x1 = rotl32(x1,b); x1 ^= x0;               \
    x0 += x1; x1 = rotl32(x1,c); x1 ^= x0;               \
    x0 += x1; x1 = rotl32(x1,d); x1 ^= x0;
    TF_R4(13,15,26,6);   x0 += k1; x1 += k2 + 1u;
    TF_R4(17,29,16,24);  x0 += k2; x1 += k0 + 2u;
    TF_R4(13,15,26,6);   x0 += k0; x1 += k1 + 3u;
    TF_R4(17,29,16,24);  x0 += k1; x1 += k2 + 4u;
    TF_R4(13,15,26,6);   x0 += k2; x1 += k0 + 5u;
#undef TF_R4
    o0 = x0; o1 = x1;
}

__device__ __forceinline__ void derive_k1(uint32_t& a, uint32_t& b) {
#if JAX_PARTITIONABLE
    tf2x32(0u, 42u, 0u, 0u, a, b);
#else
    uint32_t a0,b0,a1,b1;
    tf2x32(0u, 42u, 0u, 2u, a0, b0);
    tf2x32(0u, 42u, 1u, 3u, a1, b1);
    a = a0; b = a1;
#endif
}

__device__ __forceinline__ void derive_k2(uint32_t& a, uint32_t& b) {
#if JAX_PARTITIONABLE
    tf2x32(0u, 42u, 0u, 1u, a, b);
#else
    uint32_t a0,b0,a1,b1;
    tf2x32(0u, 42u, 0u, 2u, a0, b0);
    tf2x32(0u, 42u, 1u, 3u, a1, b1);
    a = b0; b = b1;
#endif
}

__device__ __forceinline__ uint32_t jax_bits32(uint32_t ka, uint32_t kb,
                                               uint32_t i, uint32_t n)
{
#if JAX_PARTITIONABLE
    uint32_t o0, o1;
    tf2x32(ka, kb, 0u, i, o0, o1);
    return o0 ^ o1;
#else
    uint32_t half = n >> 1;
    uint32_t j = (i < half) ? i : (i - half);
    uint32_t o0, o1;
    tf2x32(ka, kb, j, j + half, o0, o1);
    return (i < half) ? o0 : o1;
#endif
}

// ---------------------------------------------------------------------------
// Packed fp32x2 helpers (FFMA2 path — only reachable via PTX)
// ---------------------------------------------------------------------------
__device__ __forceinline__ void fma2(unsigned long long& acc,
                                     unsigned long long a,
                                     unsigned long long b)
{
    asm("fma.rn.f32x2 %0, %1, %2, %0;" : "+l"(acc) : "l"(a), "l"(b));
}
__device__ __forceinline__ unsigned long long dup2(float v)
{
    unsigned long long r;
    asm("mov.b64 %0, {%1, %1};" : "=l"(r) : "f"(v));
    return r;
}
__device__ __forceinline__ float2 unpack2(unsigned long long u)
{
    union { unsigned long long u; float2 f; } cv;
    cv.u = u;
    return cv.f;
}

// ---------------------------------------------------------------------------
// K0: zero counters, precompute w2 rowsums / b2 sum
// ---------------------------------------------------------------------------
__global__ void k_init(const float* __restrict__ W2, const float* __restrict__ b2)
{
    int t = blockIdx.x * blockDim.x + threadIdx.x;
    if (t < ND) g_cnt[t] = 0;
    if (t < DIM) {
        g_colsum[t]   = 0.f;
        g_colsumsq[t] = 0.f;
        float s = 0.f;
        #pragma unroll 8
        for (int k = 0; k < DIM; k++) s += W2[t * DIM + k];
        g_w2r[t] = s;
    }
    if (t == 0) {
        float s = 0.f;
        #pragma unroll 8
        for (int k = 0; k < DIM; k++) s += b2[k];
        g_b2sum = s;
    }
}

// ---------------------------------------------------------------------------
// K1: per-edge uniform r, scatter (m<<20 | edge_idx) into per-node buckets
// ---------------------------------------------------------------------------
__global__ void k_scatter(const int* __restrict__ DKG)
{
    int i = blockIdx.x * blockDim.x + threadIdx.x;
    if (i >= E) return;
    uint32_t ka, kb;
    derive_k1(ka, kb);
    uint32_t bits = jax_bits32(ka, kb, (uint32_t)i, (uint32_t)E);
    uint32_t m = bits >> 9;                   // r = m * 2^-23 exactly
    int head = DKG[3 * i];
    int c = atomicAdd(&g_cnt[head], 1);
    if (c < CAP)
        g_bucket[(size_t)head * CAP + c] =
            (((unsigned long long)m) << 20) | (unsigned long long)(uint32_t)i;
}

// ---------------------------------------------------------------------------
// K2: warp-per-node iterative extract-min (exact stable ranks 0..15).
//   Keys held in registers (8/lane -> deg<=256 >> observed max ~150).
// ---------------------------------------------------------------------------
__global__ __launch_bounds__(256) void k_select2()
{
    int lane = threadIdx.x & 31;
    int d = blockIdx.x * 8 + (threadIdx.x >> 5);
    int deg = g_cnt[d]; if (deg > CAP) deg = CAP;

    unsigned long long ku[8];
    #pragma unroll
    for (int s = 0; s < 8; s++) {
        int i = lane + 32 * s;
        ku[s] = (i < deg) ? g_bucket[(size_t)d * CAP + i] : ~0ull;
    }
    int nsel = (deg < S) ? deg : S;
    int myE = -1;                              // lane 'sel' keeps rank-sel edge
    for (int sel = 0; sel < S; sel++) {
        unsigned long long m = ku[0];
        #pragma unroll
        for (int s = 1; s < 8; s++) m = (ku[s] < m) ? ku[s] : m;
        #pragma unroll
        for (int o = 16; o; o >>= 1) {
            unsigned long long oth = __shfl_xor_sync(0xFFFFFFFFu, m, o);
            m = (oth < m) ? oth : m;
        }
        #pragma unroll
        for (int s = 0; s < 8; s++) if (ku[s] == m) ku[s] = ~0ull;
        if (lane == sel) myE = (m == ~0ull) ? -1 : (int)(m & 0xFFFFFull);
    }

    int e2 = myE;
    if (nsel < S && deg > 0) {                 // uniform per warp; dead in practice
        uint32_t ka, kb; derive_k2(ka, kb);
        uint32_t idx = (uint32_t)(d * S + (lane - nsel));
        uint32_t hi = jax_bits32(ka, kb, idx,          2u * ND * S);
        uint32_t lo = jax_bits32(ka, kb, idx + ND * S, 2u * ND * S);
        const uint32_t span = 2147483647u;
        uint32_t mult = (65536u * 65536u) % span;
        uint32_t off  = ((hi % span) * mult + (lo % span)) % span;
        bool need = (lane >= nsel) && (lane < S);
        int src = need ? (int)(off % (uint32_t)deg) : lane;
        int v = __shfl_sync(0xFFFFFFFFu, myE, src);
        if (need) e2 = v;
    }
    if (lane < S) g_sel[d * S + lane] = e2;
}

// ---------------------------------------------------------------------------
// K3: 8 nodes / block, 128 edges / block, 128 threads.
//   Thread tile: 8 edges x 8 cols (32 FFMA2/j, 32 u64 accumulators).
//   Per warp per j: 4x LDS.128 = 16 crossbar cycles vs 32 FFMA2 instrs
//   (= 16 SM-equivalent fma cycles) -> crossbar/fma balanced at roofline.
//   H stored scalar [j][edge]; duplicated to (h,h) via mov.b64 on ALU pipe.
// ---------------------------------------------------------------------------
__global__ __launch_bounds__(128, 4) void k_node4(
    const int*   __restrict__ DKG,
    const float* __restrict__ drug,
    const float* __restrict__ rel_emb,
    const float* __restrict__ tail_emb,
    const float* __restrict__ W1,
    const float* __restrict__ b1)
{
    extern __shared__ float sm[];
    float* Hs     = sm;                    // [64 j][128 edges]: 32 KB
    float* W1s    = sm + 8192;             // [j][c]: 16 KB
    float* de     = W1s + 4096;            // [8 nodes][64]: 2 KB
    float* b1s    = de + 512;              // 64
    float* w2s    = b1s + 64;              // 64
    float* scores = w2s + 64;              // 128
    int*   elist  = (int*)(scores + 128);  // 128
    int*   tlist  = elist + 128;           // 128
    int*   rlist  = tlist + 128;           // 128

    int tid  = threadIdx.x;
    int lane = tid & 31, w = tid >> 5;
    int g    = lane & 7, eg = lane >> 3;
    int d0   = blockIdx.x * 8;

    for (int i = tid; i < 1024; i += 128)
        ((float4*)W1s)[i] = ((const float4*)W1)[i];
    if (tid < 64) { b1s[tid] = b1[tid]; w2s[tid] = g_w2r[tid]; }
    {
        int n = tid >> 4, q = tid & 15;
        ((float4*)de)[tid] = ((const float4*)(drug + (size_t)(d0 + n) * 64))[q];
        int e = g_sel[(d0 + n) * S + q];
        elist[tid] = e;
        int ee = (e < 0) ? 0 : e;
        tlist[tid] = DKG[3 * ee + 1];
        rlist[tid] = DKG[3 * ee + 2];
    }
    __syncthreads();

    // H fill: thread <-> edge, contiguous STS.32 across the warp per j
    {
        int le = tid;
        int n  = le >> 4;
        const float4* rr = (const float4*)(rel_emb + (size_t)rlist[le] * 64);
        const float4* dn = (const float4*)(de + n * 64);
        #pragma unroll
        for (int jq = 0; jq < 16; jq++) {
            float4 rv = rr[jq], dv = dn[jq];
            int j = jq * 4;
            Hs[(j + 0) * 128 + le] = dv.x * rv.x;
            Hs[(j + 1) * 128 + le] = dv.y * rv.y;
            Hs[(j + 2) * 128 + le] = dv.z * rv.z;
            Hs[(j + 3) * 128 + le] = dv.w * rv.w;
        }
    }
    __syncthreads();

    int e0 = w * 32 + eg * 8;   // thread's 8 edges
    int c0 = g * 8;             // thread's 8 cols

    unsigned long long acc[8][4];
    {
        ulonglong2 bA = *(const ulonglong2*)(b1s + c0);
        ulonglong2 bB = *(const ulonglong2*)(b1s + c0 + 4);
        #pragma unroll
        for (int e = 0; e < 8; e++) {
            acc[e][0] = bA.x; acc[e][1] = bA.y;
            acc[e][2] = bB.x; acc[e][3] = bB.y;
        }
    }

    #pragma unroll 2
    for (int j = 0; j < 64; j++) {
        float4 h03 = *(const float4*)(Hs + j * 128 + e0);
        float4 h47 = *(const float4*)(Hs + j * 128 + e0 + 4);
        ulonglong2 wA = *(const ulonglong2*)(W1s + j * 64 + c0);
        ulonglong2 wB = *(const ulonglong2*)(W1s + j * 64 + c0 + 4);
        unsigned long long hh;
        hh = dup2(h03.x); fma2(acc[0][0],hh,wA.x); fma2(acc[0][1],hh,wA.y); fma2(acc[0][2],hh,wB.x); fma2(acc[0][3],hh,wB.y);
        hh = dup2(h03.y); fma2(acc[1][0],hh,wA.x); fma2(acc[1][1],hh,wA.y); fma2(acc[1][2],hh,wB.x); fma2(acc[1][3],hh,wB.y);
        hh = dup2(h03.z); fma2(acc[2][0],hh,wA.x); fma2(acc[2][1],hh,wA.y); fma2(acc[2][2],hh,wB.x); fma2(acc[2][3],hh,wB.y);
        hh = dup2(h03.w); fma2(acc[3][0],hh,wA.x); fma2(acc[3][1],hh,wA.y); fma2(acc[3][2],hh,wB.x); fma2(acc[3][3],hh,wB.y);
        hh = dup2(h47.x); fma2(acc[4][0],hh,wA.x); fma2(acc[4][1],hh,wA.y); fma2(acc[4][2],hh,wB.x); fma2(acc[4][3],hh,wB.y);
        hh = dup2(h47.y); fma2(acc[5][0],hh,wA.x); fma2(acc[5][1],hh,wA.y); fma2(acc[5][2],hh,wB.x); fma2(acc[5][3],hh,wB.y);
        hh = dup2(h47.z); fma2(acc[6][0],hh,wA.x); fma2(acc[6][1],hh,wA.y); fma2(acc[6][2],hh,wB.x); fma2(acc[6][3],hh,wB.y);
        hh = dup2(h47.w); fma2(acc[7][0],hh,wA.x); fma2(acc[7][1],hh,wA.y); fma2(acc[7][2],hh,wB.x); fma2(acc[7][3],hh,wB.y);
    }

    // epilogue: per-edge partial of w2 . sigmoid(y) over this thread's 8 cols
    float2 w2q[4];
    {
        float4 wa = *(const float4*)(w2s + c0);
        float4 wb = *(const float4*)(w2s + c0 + 4);
        w2q[0] = make_float2(wa.x, wa.y); w2q[1] = make_float2(wa.z, wa.w);
        w2q[2] = make_float2(wb.x, wb.y); w2q[3] = make_float2(wb.z, wb.w);
    }
    float p[8];
    #pragma unroll
    for (int e = 0; e < 8; e++) {
        float s = 0.f;
        #pragma unroll
        for (int q = 0; q < 4; q++) {
            float2 y = unpack2(acc[e][q]);
            s += w2q[q].x * __fdividef(1.f, 1.f + __expf(-y.x));
            s += w2q[q].y * __fdividef(1.f, 1.f + __expf(-y.y));
        }
        p[e] = s;
    }
    #pragma unroll
    for (int o = 1; o < 8; o <<= 1) {
        #pragma unroll
        for (int e = 0; e < 8; e++)
            p[e] += __shfl_xor_sync(0xFFFFFFFFu, p[e], o);
    }
    {
        float mysum = p[0];
        #pragma unroll
        for (int e = 1; e < 8; e++) if (g == e) mysum = p[e];  // static idx select
        int le = e0 + g;                       // 32 distinct edges per warp
        float sc = (elist[le] >= 0) ? (mysum + g_b2sum) : 0.f;
        scores[le] = sc;
    }
    __syncthreads();

    // tail accumulation: thread = (node, col-quad); sum over its 16 edges
    {
        int n = tid >> 4, cq = tid & 15;
        float4 a4 = make_float4(0.f, 0.f, 0.f, 0.f);
        #pragma unroll
        for (int k = 0; k < 16; k++) {
            int le = n * 16 + k;
            float sc = scores[le];
            float4 tv = *(const float4*)(tail_emb + (size_t)tlist[le] * 64 + cq * 4);
            a4.x += sc * tv.x; a4.y += sc * tv.y;
            a4.z += sc * tv.z; a4.w += sc * tv.w;
        }
        *(float4*)(g_neigh + (size_t)(d0 + n) * 64 + cq * 4) = a4;
    }
}

// ---------------------------------------------------------------------------
// K4: y = [drug | neigh] @ Wc + bc, plus column sum / sumsq partials
// ---------------------------------------------------------------------------
__global__ __launch_bounds__(256) void k_gemm(
    const float* __restrict__ drug,
    const float* __restrict__ Wc,
    const float* __restrict__ bc)
{
    __shared__ float Wcs[2 * DIM * DIM];      // 32 KB
    __shared__ float rsum[4][DIM], rsq[4][DIM];
    int tid = threadIdx.x;
    int k   = tid & 63;
    int ty  = tid >> 6;
    for (int i = tid; i < 2 * DIM * DIM; i += 256) Wcs[i] = Wc[i];
    __syncthreads();

    float ls = 0.f, lq = 0.f;
    int r0 = blockIdx.x * 16;
    for (int it = 0; it < 4; it++) {
        int r = r0 + it * 4 + ty;
        if (r < ND) {
            float acc = bc[k];
            #pragma unroll 8
            for (int j = 0; j < DIM; j++) acc += drug[r * DIM + j] * Wcs[j * DIM + k];
            #pragma unroll 8
            for (int j = 0; j < DIM; j++) acc += g_neigh[r * DIM + j] * Wcs[(DIM + j) * DIM + k];
            g_y[r * DIM + k] = acc;
            ls += acc; lq += acc * acc;
        }
    }
    rsum[ty][k] = ls; rsq[ty][k] = lq;
    __syncthreads();
    if (ty == 0) {
        float s = rsum[0][k] + rsum[1][k] + rsum[2][k] + rsum[3][k];
        float q = rsq[0][k]  + rsq[1][k]  + rsq[2][k]  + rsq[3][k];
        atomicAdd(&g_colsum[k],   s);
        atomicAdd(&g_colsumsq[k], q);
    }
}

// ---------------------------------------------------------------------------
// K5: batchnorm + output (stats recomputed per thread — trivially cheap)
// ---------------------------------------------------------------------------
__global__ void k_out(const float* __restrict__ gamma,
                      const float* __restrict__ beta,
                      float* __restrict__ out)
{
    int i = blockIdx.x * blockDim.x + threadIdx.x;
    if (i < ND * DIM) {
        int k = i & 63;
        float mean = g_colsum[k] * (1.f / ND);
        float var  = g_colsumsq[k] * (1.f / ND) - mean * mean;
        out[i] = gamma[k] * (g_y[i] - mean) * rsqrtf(var + 1e-5f) + beta[k];
    }
}

// ---------------------------------------------------------------------------
// Entry point. Output tuple: [HFEmbeding (10000x64) | out (10000x64) | X (10000)]
// ---------------------------------------------------------------------------
extern "C" void kernel_launch(void* const* d_in, const int* in_sizes, int n_in,
                              void* d_out, int out_size)
{
    const float* HF    = (const float*)d_in[0];
    const float* X     = (const float*)d_in[1];
    const float* drug  = (const float*)d_in[2];
    const float* rel   = (const float*)d_in[3];
    const float* tail  = (const float*)d_in[4];
    const float* W1    = (const float*)d_in[5];
    const float* b1    = (const float*)d_in[6];
    const float* W2    = (const float*)d_in[7];
    const float* b2    = (const float*)d_in[8];
    const float* Wc    = (const float*)d_in[9];
    const float* bc    = (const float*)d_in[10];
    const float* gamma = (const float*)d_in[11];
    const float* beta  = (const float*)d_in[12];
    const int*   DKG   = (const int*)d_in[13];
    float* out = (float*)d_out;

    // floats: Hs 8192 + W1s 4096 + de 512 + b1s 64 + w2s 64 + scores 128
    // ints:   elist/tlist/rlist 384
    const int node_smem = (8192 + 4096 + 512 + 64 + 64 + 128) * 4 + 384 * 4;
    cudaFuncSetAttribute(k_node4, cudaFuncAttributeMaxDynamicSharedMemorySize,
                         node_smem);   // idempotent; set on the (uncaptured) first call

    k_init    <<<(ND + 255) / 256, 256>>>(W2, b2);
    k_scatter <<<(E + 255) / 256, 256>>>(DKG);
    k_select2 <<<ND / 8, 256>>>();
    k_node4   <<<ND / 8, 128, node_smem>>>(DKG, drug, rel, tail, W1, b1);
    k_gemm    <<<(ND + 15) / 16, 256>>>(drug, Wc, bc);
    k_out     <<<(ND * DIM + 255) / 256, 256>>>(gamma, beta, out + ND * DIM);

    cudaMemcpyAsync(out,                HF, (size_t)ND * DIM * sizeof(float),
                    cudaMemcpyDeviceToDevice);
    cudaMemcpyAsync(out + 2 * ND * DIM, X,  (size_t)ND * sizeof(float),
                    cudaMemcpyDeviceToDevice);
}

// round 12
// speedup vs baseline: 1.3418x; 1.0661x over previous
#include <cuda_runtime.h>
#include <cstdint>
#include <cstddef>

// ---------------------------------------------------------------------------
// Problem constants
// ---------------------------------------------------------------------------
#define JAX_PARTITIONABLE 1   // modern JAX default (threefry_partitionable=True)

constexpr int ND  = 10000;    // N_DRUGS
constexpr int E   = 1000000;
constexpr int DIM = 64;
constexpr int S   = 16;       // SAMPLE_SIZE
constexpr int CAP = 192;      // per-node bucket capacity (max deg ~150 here)

// ---------------------------------------------------------------------------
// Static device scratch (no runtime allocation allowed)
// ---------------------------------------------------------------------------
__device__ unsigned long long g_bucket[(size_t)ND * CAP];  // (m<<20)|edge_idx
__device__ int   g_cnt[ND];
__device__ int   g_sel[ND * S];      // ALL 16 slots valid after select (-1 if none)
__device__ float g_neigh[ND * DIM];
__device__ float g_y[ND * DIM];
__device__ float g_colsum[DIM];
__device__ float g_colsumsq[DIM];
__device__ float g_w2r[DIM];         // rowsum of W2
__device__ float g_b2sum;

// ---------------------------------------------------------------------------
// Threefry2x32 (bit-exact JAX replica)
// ---------------------------------------------------------------------------
__device__ __forceinline__ uint32_t rotl32(uint32_t v, int r) {
    return (v << r) | (v >> (32 - r));
}

__device__ __forceinline__ void tf2x32(uint32_t k0, uint32_t k1,
                                       uint32_t x0, uint32_t x1,
                                       uint32_t& o0, uint32_t& o1)
{
    uint32_t k2 = k0 ^ k1 ^ 0x1BD11BDAu;
    x0 += k0; x1 += k1;
#define TF_R4(a,b,c,d)                                   \
    x0 += x1; x1 = rotl32(x1,a); x1 ^= x0;               \
    x0 += x1; x1 = rotl32(x1,b); x1 ^= x0;               \
    x0 += x1; x1 = rotl32(x1,c); x1 ^= x0;               \
    x0 += x1; x1 = rotl32(x1,d); x1 ^= x0;
    TF_R4(13,15,26,6);   x0 += k1; x1 += k2 + 1u;
    TF_R4(17,29,16,24);  x0 += k2; x1 += k0 + 2u;
    TF_R4(13,15,26,6);   x0 += k0; x1 += k1 + 3u;
    TF_R4(17,29,16,24);  x0 += k1; x1 += k2 + 4u;
    TF_R4(13,15,26,6);   x0 += k2; x1 += k0 + 5u;
#undef TF_R4
    o0 = x0; o1 = x1;
}

__device__ __forceinline__ void derive_k1(uint32_t& a, uint32_t& b) {
#if JAX_PARTITIONABLE
    tf2x32(0u, 42u, 0u, 0u, a, b);
#else
    uint32_t a0,b0,a1,b1;
    tf2x32(0u, 42u, 0u, 2u, a0, b0);
    tf2x32(0u, 42u, 1u, 3u, a1, b1);
    a = a0; b = a1;
#endif
}

__device__ __forceinline__ void derive_k2(uint32_t& a, uint32_t& b) {
#if JAX_PARTITIONABLE
    tf2x32(0u, 42u, 0u, 1u, a, b);
#else
    uint32_t a0,b0,a1,b1;
    tf2x32(0u, 42u, 0u, 2u, a0, b0);
    tf2x32(0u, 42u, 1u, 3u, a1, b1);
    a = b0; b = b1;
#endif
}

__device__ __forceinline__ uint32_t jax_bits32(uint32_t ka, uint32_t kb,
                                               uint32_t i, uint32_t n)
{
#if JAX_PARTITIONABLE
    uint32_t o0, o1;
    tf2x32(ka, kb, 0u, i, o0, o1);
    return o0 ^ o1;
#else
    uint32_t half = n >> 1;
    uint32_t j = (i < half) ? i : (i - half);
    uint32_t o0, o1;
    tf2x32(ka, kb, j, j + half, o0, o1);
    return (i < half) ? o0 : o1;
#endif
}

// ---------------------------------------------------------------------------
// Packed fp32x2 helpers (FFMA2 path — only reachable via PTX)
// ---------------------------------------------------------------------------
__device__ __forceinline__ void fma2(unsigned long long& acc,
                                     unsigned long long a,
                                     unsigned long long b)
{
    asm("fma.rn.f32x2 %0, %1, %2, %0;" : "+l"(acc) : "l"(a), "l"(b));
}
__device__ __forceinline__ unsigned long long dup2(float v)
{
    unsigned long long r;
    asm("mov.b64 %0, {%1, %1};" : "=l"(r) : "f"(v));
    return r;
}
__device__ __forceinline__ float2 unpack2(unsigned long long u)
{
    union { unsigned long long u; float2 f; } cv;
    cv.u = u;
    return cv.f;
}

// ---------------------------------------------------------------------------
// K1: per-edge uniform r, scatter (m<<20 | edge_idx) into per-node buckets
// ---------------------------------------------------------------------------
__global__ void k_scatter(const int* __restrict__ DKG)
{
    int i = blockIdx.x * blockDim.x + threadIdx.x;
    if (i >= E) return;
    uint32_t ka, kb;
    derive_k1(ka, kb);
    uint32_t bits = jax_bits32(ka, kb, (uint32_t)i, (uint32_t)E);
    uint32_t m = bits >> 9;                   // r = m * 2^-23 exactly
    int head = __ldg(&DKG[3 * i]);
    int c = atomicAdd(&g_cnt[head], 1);
    if (c < CAP)
        g_bucket[(size_t)head * CAP + c] =
            (((unsigned long long)m) << 20) | (unsigned long long)(uint32_t)i;
}

// ---------------------------------------------------------------------------
// K2: warp-per-node iterative extract-min (exact stable ranks 0..15).
//   Keys in registers (6/lane -> deg<=192 >> observed max ~150).
//   Also: clears g_cnt for the NEXT call, and block 0 computes w2 rowsums,
//   b2 sum and zeroes the batchnorm accumulators (replaces old k_init).
// ---------------------------------------------------------------------------
__global__ __launch_bounds__(256) void k_select2(
    const float* __restrict__ W2, const float* __restrict__ b2)
{
    int lane = threadIdx.x & 31;
    int d = blockIdx.x * 8 + (threadIdx.x >> 5);
    int deg = g_cnt[d]; if (deg > CAP) deg = CAP;
    if (lane == 0) g_cnt[d] = 0;               // reset for next graph replay

    unsigned long long ku[6];
    #pragma unroll
    for (int s = 0; s < 6; s++) {
        int i = lane + 32 * s;
        ku[s] = (i < deg) ? g_bucket[(size_t)d * CAP + i] : ~0ull;
    }
    int nsel = (deg < S) ? deg : S;
    int myE = -1;                              // lane 'sel' keeps rank-sel edge
    for (int sel = 0; sel < S; sel++) {
        unsigned long long m = ku[0];
        #pragma unroll
        for (int s = 1; s < 6; s++) m = (ku[s] < m) ? ku[s] : m;
        #pragma unroll
        for (int o = 16; o; o >>= 1) {
            unsigned long long oth = __shfl_xor_sync(0xFFFFFFFFu, m, o);
            m = (oth < m) ? oth : m;
        }
        #pragma unroll
        for (int s = 0; s < 6; s++) if (ku[s] == m) ku[s] = ~0ull;
        if (lane == sel) myE = (m == ~0ull) ? -1 : (int)(m & 0xFFFFFull);
    }

    int e2 = myE;
    if (nsel < S && deg > 0) {                 // uniform per warp; dead in practice
        uint32_t ka, kb; derive_k2(ka, kb);
        uint32_t idx = (uint32_t)(d * S + (lane - nsel));
        uint32_t hi = jax_bits32(ka, kb, idx,          2u * ND * S);
        uint32_t lo = jax_bits32(ka, kb, idx + ND * S, 2u * ND * S);
        const uint32_t span = 2147483647u;
        uint32_t mult = (65536u * 65536u) % span;
        uint32_t off  = ((hi % span) * mult + (lo % span)) % span;
        bool need = (lane >= nsel) && (lane < S);
        int src = need ? (int)(off % (uint32_t)deg) : lane;
        int v = __shfl_sync(0xFFFFFFFFu, myE, src);
        if (need) e2 = v;
    }
    if (lane < S) g_sel[d * S + lane] = e2;

    // ---- block 0 extras (old k_init) ----
    if (blockIdx.x == 0) {
        int t = threadIdx.x;
        if (t < DIM) {
            g_colsum[t]   = 0.f;
            g_colsumsq[t] = 0.f;
            float s = 0.f;
            #pragma unroll 8
            for (int k = 0; k < DIM; k++) s += W2[t * DIM + k];
            g_w2r[t] = s;
        }
        if (t == 64) {
            float s = 0.f;
            #pragma unroll 8
            for (int k = 0; k < DIM; k++) s += b2[k];
            g_b2sum = s;
        }
    }
}

// ---------------------------------------------------------------------------
// K3: 8 nodes / block, 128 edges / block, 128 threads.
//   Thread tile: 8 edges x 8 cols (32 FFMA2/j).
//   W repacked CONFLICT-FREE: Wp[j*64 + half*32 + g*4 + q] = W1[j][g*8+half*4+q]
//   -> warp's 8 wA addrs are 16B-consecutive in ONE 128B bank row (4 wf),
//      same for wB. Per warp per j: 16 LDS wf vs 16 SM-fma cycles: balanced.
// ---------------------------------------------------------------------------
__global__ __launch_bounds__(128, 4) void k_node5(
    const int*   __restrict__ DKG,
    const float* __restrict__ drug,
    const float* __restrict__ rel_emb,
    const float* __restrict__ tail_emb,
    const float* __restrict__ W1,
    const float* __restrict__ b1)
{
    extern __shared__ float sm[];
    float* Hs     = sm;                    // [64 j][128 edges]: 32 KB
    float* Wp     = sm + 8192;             // repacked W1 [j][64]: 16 KB
    float* de     = Wp + 4096;             // [8 nodes][64]: 2 KB
    float* b1s    = de + 512;              // 64
    float* w2s    = b1s + 64;              // 64
    float* scores = w2s + 64;              // 128
    int*   elist  = (int*)(scores + 128);  // 128
    int*   tlist  = elist + 128;           // 128
    int*   rlist  = tlist + 128;           // 128

    int tid  = threadIdx.x;
    int lane = tid & 31, w = tid >> 5;
    int g    = lane & 7, eg = lane >> 3;
    int d0   = blockIdx.x * 8;

    // W repack fill: float4 i -> j = i>>4, t = i&15, half = t>>3, gg = t&7
    //   src  = W1 float4 (j*16 + gg*2 + half), dst = Wp float4 (j*16 + half*8 + gg)
    for (int i = tid; i < 1024; i += 128) {
        int j = i >> 4, t = i & 15;
        int half = t >> 3, gg = t & 7;
        ((float4*)Wp)[j * 16 + half * 8 + gg] =
            ((const float4*)W1)[j * 16 + gg * 2 + half];
    }
    if (tid < 64) { b1s[tid] = b1[tid]; w2s[tid] = g_w2r[tid]; }
    {
        int n = tid >> 4, q = tid & 15;
        ((float4*)de)[tid] = ((const float4*)(drug + (size_t)(d0 + n) * 64))[q];
        int e = g_sel[(d0 + n) * S + q];
        elist[tid] = e;
        int ee = (e < 0) ? 0 : e;
        tlist[tid] = DKG[3 * ee + 1];
        rlist[tid] = DKG[3 * ee + 2];
    }
    __syncthreads();

    // H fill: thread <-> edge, contiguous STS.32 across the warp per j
    {
        int le = tid;
        int n  = le >> 4;
        const float4* rr = (const float4*)(rel_emb + (size_t)rlist[le] * 64);
        const float4* dn = (const float4*)(de + n * 64);
        #pragma unroll
        for (int jq = 0; jq < 16; jq++) {
            float4 rv = rr[jq], dv = dn[jq];
            int j = jq * 4;
            Hs[(j + 0) * 128 + le] = dv.x * rv.x;
            Hs[(j + 1) * 128 + le] = dv.y * rv.y;
            Hs[(j + 2) * 128 + le] = dv.z * rv.z;
            Hs[(j + 3) * 128 + le] = dv.w * rv.w;
        }
    }
    __syncthreads();

    int e0 = w * 32 + eg * 8;   // thread's 8 edges
    int c0 = g * 8;             // thread's 8 cols (logical)

    unsigned long long acc[8][4];
    {
        ulonglong2 bA = *(const ulonglong2*)(b1s + c0);
        ulonglong2 bB = *(const ulonglong2*)(b1s + c0 + 4);
        #pragma unroll
        for (int e = 0; e < 8; e++) {
            acc[e][0] = bA.x; acc[e][1] = bA.y;
            acc[e][2] = bB.x; acc[e][3] = bB.y;
        }
    }

    #pragma unroll 2
    for (int j = 0; j < 64; j++) {
        float4 h03 = *(const float4*)(Hs + j * 128 + e0);
        float4 h47 = *(const float4*)(Hs + j * 128 + e0 + 4);
        // conflict-free repacked W: wA covers cols g*8..+3, wB cols g*8+4..+7
        ulonglong2 wA = *(const ulonglong2*)(Wp + j * 64 + g * 4);
        ulonglong2 wB = *(const ulonglong2*)(Wp + j * 64 + 32 + g * 4);
        unsigned long long hh;
        hh = dup2(h03.x); fma2(acc[0][0],hh,wA.x); fma2(acc[0][1],hh,wA.y); fma2(acc[0][2],hh,wB.x); fma2(acc[0][3],hh,wB.y);
        hh = dup2(h03.y); fma2(acc[1][0],hh,wA.x); fma2(acc[1][1],hh,wA.y); fma2(acc[1][2],hh,wB.x); fma2(acc[1][3],hh,wB.y);
        hh = dup2(h03.z); fma2(acc[2][0],hh,wA.x); fma2(acc[2][1],hh,wA.y); fma2(acc[2][2],hh,wB.x); fma2(acc[2][3],hh,wB.y);
        hh = dup2(h03.w); fma2(acc[3][0],hh,wA.x); fma2(acc[3][1],hh,wA.y); fma2(acc[3][2],hh,wB.x); fma2(acc[3][3],hh,wB.y);
        hh = dup2(h47.x); fma2(acc[4][0],hh,wA.x); fma2(acc[4][1],hh,wA.y); fma2(acc[4][2],hh,wB.x); fma2(acc[4][3],hh,wB.y);
        hh = dup2(h47.y); fma2(acc[5][0],hh,wA.x); fma2(acc[5][1],hh,wA.y); fma2(acc[5][2],hh,wB.x); fma2(acc[5][3],hh,wB.y);
        hh = dup2(h47.z); fma2(acc[6][0],hh,wA.x); fma2(acc[6][1],hh,wA.y); fma2(acc[6][2],hh,wB.x); fma2(acc[6][3],hh,wB.y);
        hh = dup2(h47.w); fma2(acc[7][0],hh,wA.x); fma2(acc[7][1],hh,wA.y); fma2(acc[7][2],hh,wB.x); fma2(acc[7][3],hh,wB.y);
    }

    // epilogue: per-edge partial of w2 . sigmoid(y) over this thread's 8 cols
    float2 w2q[4];
    {
        float4 wa = *(const float4*)(w2s + c0);
        float4 wb = *(const float4*)(w2s + c0 + 4);
        w2q[0] = make_float2(wa.x, wa.y); w2q[1] = make_float2(wa.z, wa.w);
        w2q[2] = make_float2(wb.x, wb.y); w2q[3] = make_float2(wb.z, wb.w);
    }
    float p[8];
    #pragma unroll
    for (int e = 0; e < 8; e++) {
        float s = 0.f;
        #pragma unroll
        for (int q = 0; q < 4; q++) {
            float2 y = unpack2(acc[e][q]);
            s += w2q[q].x * __fdividef(1.f, 1.f + __expf(-y.x));
            s += w2q[q].y * __fdividef(1.f, 1.f + __expf(-y.y));
        }
        p[e] = s;
    }
    #pragma unroll
    for (int o = 1; o < 8; o <<= 1) {
        #pragma unroll
        for (int e = 0; e < 8; e++)
            p[e] += __shfl_xor_sync(0xFFFFFFFFu, p[e], o);
    }
    {
        float mysum = p[0];
        #pragma unroll
        for (int e = 1; e < 8; e++) if (g == e) mysum = p[e];  // static idx select
        int le = e0 + g;                       // 32 distinct edges per warp
        float sc = (elist[le] >= 0) ? (mysum + g_b2sum) : 0.f;
        scores[le] = sc;
    }
    __syncthreads();

    // tail accumulation: thread = (node, col-quad); sum over its 16 edges
    {
        int n = tid >> 4, cq = tid & 15;
        float4 a4 = make_float4(0.f, 0.f, 0.f, 0.f);
        #pragma unroll
        for (int k = 0; k < 16; k++) {
            int le = n * 16 + k;
            float sc = scores[le];
            float4 tv = *(const float4*)(tail_emb + (size_t)tlist[le] * 64 + cq * 4);
            a4.x += sc * tv.x; a4.y += sc * tv.y;
            a4.z += sc * tv.z; a4.w += sc * tv.w;
        }
        *(float4*)(g_neigh + (size_t)(d0 + n) * 64 + cq * 4) = a4;
    }
}

// ---------------------------------------------------------------------------
// K4: y = [drug | neigh] @ Wc + bc, plus column sum / sumsq partials
// ---------------------------------------------------------------------------
__global__ __launch_bounds__(256) void k_gemm(
    const float* __restrict__ drug,
    const float* __restrict__ Wc,
    const float* __restrict__ bc)
{
    __shared__ float Wcs[2 * DIM * DIM];      // 32 KB
    __shared__ float rsum[4][DIM], rsq[4][DIM];
    int tid = threadIdx.x;
    int k   = tid & 63;
    int ty  = tid >> 6;
    for (int i = tid; i < 2 * DIM * DIM; i += 256) Wcs[i] = Wc[i];
    __syncthreads();

    float ls = 0.f, lq = 0.f;
    int r0 = blockIdx.x * 16;
    for (int it = 0; it < 4; it++) {
        int r = r0 + it * 4 + ty;
        if (r < ND) {
            float acc = bc[k];
            #pragma unroll 8
            for (int j = 0; j < DIM; j++) acc += drug[r * DIM + j] * Wcs[j * DIM + k];
            #pragma unroll 8
            for (int j = 0; j < DIM; j++) acc += g_neigh[r * DIM + j] * Wcs[(DIM + j) * DIM + k];
            g_y[r * DIM + k] = acc;
            ls += acc; lq += acc * acc;
        }
    }
    rsum[ty][k] = ls; rsq[ty][k] = lq;
    __syncthreads();
    if (ty == 0) {
        float s = rsum[0][k] + rsum[1][k] + rsum[2][k] + rsum[3][k];
        float q = rsq[0][k]  + rsq[1][k]  + rsq[2][k]  + rsq[3][k];
        atomicAdd(&g_colsum[k],   s);
        atomicAdd(&g_colsumsq[k], q);
    }
}

// ---------------------------------------------------------------------------
// K5: batchnorm + output (stats recomputed per thread — trivially cheap)
// ---------------------------------------------------------------------------
__global__ void k_out(const float* __restrict__ gamma,
                      const float* __restrict__ beta,
                      float* __restrict__ out)
{
    int i = blockIdx.x * blockDim.x + threadIdx.x;
    if (i < ND * DIM) {
        int k = i & 63;
        float mean = g_colsum[k] * (1.f / ND);
        float var  = g_colsumsq[k] * (1.f / ND) - mean * mean;
        out[i] = gamma[k] * (g_y[i] - mean) * rsqrtf(var + 1e-5f) + beta[k];
    }
}

// ---------------------------------------------------------------------------
// Entry point. Output tuple: [HFEmbeding (10000x64) | out (10000x64) | X (10000)]
// ---------------------------------------------------------------------------
extern "C" void kernel_launch(void* const* d_in, const int* in_sizes, int n_in,
                              void* d_out, int out_size)
{
    const float* HF    = (const float*)d_in[0];
    const float* X     = (const float*)d_in[1];
    const float* drug  = (const float*)d_in[2];
    const float* rel   = (const float*)d_in[3];
    const float* tail  = (const float*)d_in[4];
    const float* W1    = (const float*)d_in[5];
    const float* b1    = (const float*)d_in[6];
    const float* W2    = (const float*)d_in[7];
    const float* b2    = (const float*)d_in[8];
    const float* Wc    = (const float*)d_in[9];
    const float* bc    = (const float*)d_in[10];
    const float* gamma = (const float*)d_in[11];
    const float* beta  = (const float*)d_in[12];
    const int*   DKG   = (const int*)d_in[13];
    float* out = (float*)d_out;

    // floats: Hs 8192 + Wp 4096 + de 512 + b1s 64 + w2s 64 + scores 128
    // ints:   elist/tlist/rlist 384
    const int node_smem = (8192 + 4096 + 512 + 64 + 64 + 128) * 4 + 384 * 4;
    cudaFuncSetAttribute(k_node5, cudaFuncAttributeMaxDynamicSharedMemorySize,
                         node_smem);   // idempotent; set on the (uncaptured) first call

    k_scatter <<<(E + 255) / 256, 256>>>(DKG);
    k_select2 <<<ND / 8, 256>>>(W2, b2);
    k_node5   <<<ND / 8, 128, node_smem>>>(DKG, drug, rel, tail, W1, b1);
    k_gemm    <<<(ND + 15) / 16, 256>>>(drug, Wc, bc);
    k_out     <<<(ND * DIM + 255) / 256, 256>>>(gamma, beta, out + ND * DIM);

    cudaMemcpyAsync(out,                HF, (size_t)ND * DIM * sizeof(float),
                    cudaMemcpyDeviceToDevice);
    cudaMemcpyAsync(out + 2 * ND * DIM, X,  (size_t)ND * sizeof(float),
                    cudaMemcpyDeviceToDevice);
}

// round 13
// speedup vs baseline: 1.5566x; 1.1601x over previous
#include <cuda_runtime.h>
#include <cstdint>
#include <cstddef>

// ---------------------------------------------------------------------------
// Problem constants
// ---------------------------------------------------------------------------
#define JAX_PARTITIONABLE 1   // modern JAX default (threefry_partitionable=True)

constexpr int ND  = 10000;    // N_DRUGS
constexpr int E   = 1000000;
constexpr int DIM = 64;
constexpr int S   = 16;       // SAMPLE_SIZE
constexpr int CAP = 192;      // per-node bucket capacity (max deg ~150 here)

// ---------------------------------------------------------------------------
// Static device scratch (no runtime allocation allowed)
// ---------------------------------------------------------------------------
__device__ unsigned long long g_bucket[(size_t)ND * CAP];  // (m<<20)|edge_idx
__device__ int   g_cnt[ND];
__device__ int   g_sel[ND * S];      // ALL 16 slots valid after select (-1 if none)
__device__ float g_neigh[ND * DIM];
__device__ float g_y[ND * DIM];
__device__ float g_colsum[DIM];
__device__ float g_colsumsq[DIM];
__device__ float g_w2r[DIM];         // rowsum of W2
__device__ float g_b2sum;

// ---------------------------------------------------------------------------
// Threefry2x32 (bit-exact JAX replica)
// ---------------------------------------------------------------------------
__device__ __forceinline__ uint32_t rotl32(uint32_t v, int r) {
    return (v << r) | (v >> (32 - r));
}

__device__ __forceinline__ void tf2x32(uint32_t k0, uint32_t k1,
                                       uint32_t x0, uint32_t x1,
                                       uint32_t& o0, uint32_t& o1)
{
    uint32_t k2 = k0 ^ k1 ^ 0x1BD11BDAu;
    x0 += k0; x1 += k1;
#define TF_R4(a,b,c,d)                                   \
    x0 += x1; x1 = rotl32(x1,a); x1 ^= x0;               \
    x0 += x1; x1 = rotl32(x1,b); x1 ^= x0;               \
    x0 += x1; x1 = rotl32(x1,c); x1 ^= x0;               \
    x0 += x1; x1 = rotl32(x1,d); x1 ^= x0;
    TF_R4(13,15,26,6);   x0 += k1; x1 += k2 + 1u;
    TF_R4(17,29,16,24);  x0 += k2; x1 += k0 + 2u;
    TF_R4(13,15,26,6);   x0 += k0; x1 += k1 + 3u;
    TF_R4(17,29,16,24);  x0 += k1; x1 += k2 + 4u;
    TF_R4(13,15,26,6);   x0 += k2; x1 += k0 + 5u;
#undef TF_R4
    o0 = x0; o1 = x1;
}

__device__ __forceinline__ void derive_k1(uint32_t& a, uint32_t& b) {
#if JAX_PARTITIONABLE
    tf2x32(0u, 42u, 0u, 0u, a, b);
#else
    uint32_t a0,b0,a1,b1;
    tf2x32(0u, 42u, 0u, 2u, a0, b0);
    tf2x32(0u, 42u, 1u, 3u, a1, b1);
    a = a0; b = a1;
#endif
}

__device__ __forceinline__ void derive_k2(uint32_t& a, uint32_t& b) {
#if JAX_PARTITIONABLE
    tf2x32(0u, 42u, 0u, 1u, a, b);
#else
    uint32_t a0,b0,a1,b1;
    tf2x32(0u, 42u, 0u, 2u, a0, b0);
    tf2x32(0u, 42u, 1u, 3u, a1, b1);
    a = b0; b = b1;
#endif
}

__device__ __forceinline__ uint32_t jax_bits32(uint32_t ka, uint32_t kb,
                                               uint32_t i, uint32_t n)
{
#if JAX_PARTITIONABLE
    uint32_t o0, o1;
    tf2x32(ka, kb, 0u, i, o0, o1);
    return o0 ^ o1;
#else
    uint32_t half = n >> 1;
    uint32_t j = (i < half) ? i : (i - half);
    uint32_t o0, o1;
    tf2x32(ka, kb, j, j + half, o0, o1);
    return (i < half) ? o0 : o1;
#endif
}

// ---------------------------------------------------------------------------
// Packed fp32x2 helpers (FFMA2 path — only reachable via PTX)
// ---------------------------------------------------------------------------
__device__ __forceinline__ void fma2(unsigned long long& acc,
                                     unsigned long long a,
                                     unsigned long long b)
{
    asm("fma.rn.f32x2 %0, %1, %2, %0;" : "+l"(acc) : "l"(a), "l"(b));
}
__device__ __forceinline__ unsigned long long dup2(float v)
{
    unsigned long long r;
    asm("mov.b64 %0, {%1, %1};" : "=l"(r) : "f"(v));
    return r;
}
__device__ __forceinline__ float2 unpack2(unsigned long long u)
{
    union { unsigned long long u; float2 f; } cv;
    cv.u = u;
    return cv.f;
}

// ---------------------------------------------------------------------------
// K1: per-edge uniform r, scatter (m<<20 | edge_idx) into per-node buckets
// ---------------------------------------------------------------------------
__global__ void k_scatter(const int* __restrict__ DKG)
{
    int i = blockIdx.x * blockDim.x + threadIdx.x;
    if (i >= E) return;
    uint32_t ka, kb;
    derive_k1(ka, kb);
    uint32_t bits = jax_bits32(ka, kb, (uint32_t)i, (uint32_t)E);
    uint32_t m = bits >> 9;                   // r = m * 2^-23 exactly
    int head = __ldg(&DKG[3 * i]);
    int c = atomicAdd(&g_cnt[head], 1);
    if (c < CAP)
        g_bucket[(size_t)head * CAP + c] =
            (((unsigned long long)m) << 20) | (unsigned long long)(uint32_t)i;
}

// ---------------------------------------------------------------------------
// K2: warp-per-node iterative extract-min (exact stable ranks 0..15).
//   Also clears g_cnt for the next replay; block 0 does the old k_init work.
// ---------------------------------------------------------------------------
__global__ __launch_bounds__(256) void k_select2(
    const float* __restrict__ W2, const float* __restrict__ b2)
{
    int lane = threadIdx.x & 31;
    int d = blockIdx.x * 8 + (threadIdx.x >> 5);
    int deg = g_cnt[d]; if (deg > CAP) deg = CAP;
    if (lane == 0) g_cnt[d] = 0;               // reset for next graph replay

    unsigned long long ku[6];
    #pragma unroll
    for (int s = 0; s < 6; s++) {
        int i = lane + 32 * s;
        ku[s] = (i < deg) ? g_bucket[(size_t)d * CAP + i] : ~0ull;
    }
    int nsel = (deg < S) ? deg : S;
    int myE = -1;                              // lane 'sel' keeps rank-sel edge
    for (int sel = 0; sel < S; sel++) {
        unsigned long long m = ku[0];
        #pragma unroll
        for (int s = 1; s < 6; s++) m = (ku[s] < m) ? ku[s] : m;
        #pragma unroll
        for (int o = 16; o; o >>= 1) {
            unsigned long long oth = __shfl_xor_sync(0xFFFFFFFFu, m, o);
            m = (oth < m) ? oth : m;
        }
        #pragma unroll
        for (int s = 0; s < 6; s++) if (ku[s] == m) ku[s] = ~0ull;
        if (lane == sel) myE = (m == ~0ull) ? -1 : (int)(m & 0xFFFFFull);
    }

    int e2 = myE;
    if (nsel < S && deg > 0) {                 // uniform per warp; dead in practice
        uint32_t ka, kb; derive_k2(ka, kb);
        uint32_t idx = (uint32_t)(d * S + (lane - nsel));
        uint32_t hi = jax_bits32(ka, kb, idx,          2u * ND * S);
        uint32_t lo = jax_bits32(ka, kb, idx + ND * S, 2u * ND * S);
        const uint32_t span = 2147483647u;
        uint32_t mult = (65536u * 65536u) % span;
        uint32_t off  = ((hi % span) * mult + (lo % span)) % span;
        bool need = (lane >= nsel) && (lane < S);
        int src = need ? (int)(off % (uint32_t)deg) : lane;
        int v = __shfl_sync(0xFFFFFFFFu, myE, src);
        if (need) e2 = v;
    }
    if (lane < S) g_sel[d * S + lane] = e2;

    // ---- block 0 extras (old k_init) ----
    if (blockIdx.x == 0) {
        int t = threadIdx.x;
        if (t < DIM) {
            g_colsum[t]   = 0.f;
            g_colsumsq[t] = 0.f;
            float s = 0.f;
            #pragma unroll 8
            for (int k = 0; k < DIM; k++) s += W2[t * DIM + k];
            g_w2r[t] = s;
        }
        if (t == 64) {
            float s = 0.f;
            #pragma unroll 8
            for (int k = 0; k < DIM; k++) s += b2[k];
            g_b2sum = s;
        }
    }
}

// ---------------------------------------------------------------------------
// K3: 8 nodes / block, 128 edges / block, 128 threads (unchanged from R12).
// ---------------------------------------------------------------------------
__global__ __launch_bounds__(128, 4) void k_node5(
    const int*   __restrict__ DKG,
    const float* __restrict__ drug,
    const float* __restrict__ rel_emb,
    const float* __restrict__ tail_emb,
    const float* __restrict__ W1,
    const float* __restrict__ b1)
{
    extern __shared__ float sm[];
    float* Hs     = sm;                    // [64 j][128 edges]: 32 KB
    float* Wp     = sm + 8192;             // repacked W1 [j][64]: 16 KB
    float* de     = Wp + 4096;             // [8 nodes][64]: 2 KB
    float* b1s    = de + 512;              // 64
    float* w2s    = b1s + 64;              // 64
    float* scores = w2s + 64;              // 128
    int*   elist  = (int*)(scores + 128);  // 128
    int*   tlist  = elist + 128;           // 128
    int*   rlist  = tlist + 128;           // 128

    int tid  = threadIdx.x;
    int lane = tid & 31, w = tid >> 5;
    int g    = lane & 7, eg = lane >> 3;
    int d0   = blockIdx.x * 8;

    for (int i = tid; i < 1024; i += 128) {
        int j = i >> 4, t = i & 15;
        int half = t >> 3, gg = t & 7;
        ((float4*)Wp)[j * 16 + half * 8 + gg] =
            ((const float4*)W1)[j * 16 + gg * 2 + half];
    }
    if (tid < 64) { b1s[tid] = b1[tid]; w2s[tid] = g_w2r[tid]; }
    {
        int n = tid >> 4, q = tid & 15;
        ((float4*)de)[tid] = ((const float4*)(drug + (size_t)(d0 + n) * 64))[q];
        int e = g_sel[(d0 + n) * S + q];
        elist[tid] = e;
        int ee = (e < 0) ? 0 : e;
        tlist[tid] = DKG[3 * ee + 1];
        rlist[tid] = DKG[3 * ee + 2];
    }
    __syncthreads();

    {
        int le = tid;
        int n  = le >> 4;
        const float4* rr = (const float4*)(rel_emb + (size_t)rlist[le] * 64);
        const float4* dn = (const float4*)(de + n * 64);
        #pragma unroll
        for (int jq = 0; jq < 16; jq++) {
            float4 rv = rr[jq], dv = dn[jq];
            int j = jq * 4;
            Hs[(j + 0) * 128 + le] = dv.x * rv.x;
            Hs[(j + 1) * 128 + le] = dv.y * rv.y;
            Hs[(j + 2) * 128 + le] = dv.z * rv.z;
            Hs[(j + 3) * 128 + le] = dv.w * rv.w;
        }
    }
    __syncthreads();

    int e0 = w * 32 + eg * 8;   // thread's 8 edges
    int c0 = g * 8;             // thread's 8 cols (logical)

    unsigned long long acc[8][4];
    {
        ulonglong2 bA = *(const ulonglong2*)(b1s + c0);
        ulonglong2 bB = *(const ulonglong2*)(b1s + c0 + 4);
        #pragma unroll
        for (int e = 0; e < 8; e++) {
            acc[e][0] = bA.x; acc[e][1] = bA.y;
            acc[e][2] = bB.x; acc[e][3] = bB.y;
        }
    }

    #pragma unroll 2
    for (int j = 0; j < 64; j++) {
        float4 h03 = *(const float4*)(Hs + j * 128 + e0);
        float4 h47 = *(const float4*)(Hs + j * 128 + e0 + 4);
        ulonglong2 wA = *(const ulonglong2*)(Wp + j * 64 + g * 4);
        ulonglong2 wB = *(const ulonglong2*)(Wp + j * 64 + 32 + g * 4);
        unsigned long long hh;
        hh = dup2(h03.x); fma2(acc[0][0],hh,wA.x); fma2(acc[0][1],hh,wA.y); fma2(acc[0][2],hh,wB.x); fma2(acc[0][3],hh,wB.y);
        hh = dup2(h03.y); fma2(acc[1][0],hh,wA.x); fma2(acc[1][1],hh,wA.y); fma2(acc[1][2],hh,wB.x); fma2(acc[1][3],hh,wB.y);
        hh = dup2(h03.z); fma2(acc[2][0],hh,wA.x); fma2(acc[2][1],hh,wA.y); fma2(acc[2][2],hh,wB.x); fma2(acc[2][3],hh,wB.y);
        hh = dup2(h03.w); fma2(acc[3][0],hh,wA.x); fma2(acc[3][1],hh,wA.y); fma2(acc[3][2],hh,wB.x); fma2(acc[3][3],hh,wB.y);
        hh = dup2(h47.x); fma2(acc[4][0],hh,wA.x); fma2(acc[4][1],hh,wA.y); fma2(acc[4][2],hh,wB.x); fma2(acc[4][3],hh,wB.y);
        hh = dup2(h47.y); fma2(acc[5][0],hh,wA.x); fma2(acc[5][1],hh,wA.y); fma2(acc[5][2],hh,wB.x); fma2(acc[5][3],hh,wB.y);
        hh = dup2(h47.z); fma2(acc[6][0],hh,wA.x); fma2(acc[6][1],hh,wA.y); fma2(acc[6][2],hh,wB.x); fma2(acc[6][3],hh,wB.y);
        hh = dup2(h47.w); fma2(acc[7][0],hh,wA.x); fma2(acc[7][1],hh,wA.y); fma2(acc[7][2],hh,wB.x); fma2(acc[7][3],hh,wB.y);
    }

    float2 w2q[4];
    {
        float4 wa = *(const float4*)(w2s + c0);
        float4 wb = *(const float4*)(w2s + c0 + 4);
        w2q[0] = make_float2(wa.x, wa.y); w2q[1] = make_float2(wa.z, wa.w);
        w2q[2] = make_float2(wb.x, wb.y); w2q[3] = make_float2(wb.z, wb.w);
    }
    float p[8];
    #pragma unroll
    for (int e = 0; e < 8; e++) {
        float s = 0.f;
        #pragma unroll
        for (int q = 0; q < 4; q++) {
            float2 y = unpack2(acc[e][q]);
            s += w2q[q].x * __fdividef(1.f, 1.f + __expf(-y.x));
            s += w2q[q].y * __fdividef(1.f, 1.f + __expf(-y.y));
        }
        p[e] = s;
    }
    #pragma unroll
    for (int o = 1; o < 8; o <<= 1) {
        #pragma unroll
        for (int e = 0; e < 8; e++)
            p[e] += __shfl_xor_sync(0xFFFFFFFFu, p[e], o);
    }
    {
        float mysum = p[0];
        #pragma unroll
        for (int e = 1; e < 8; e++) if (g == e) mysum = p[e];
        int le = e0 + g;
        float sc = (elist[le] >= 0) ? (mysum + g_b2sum) : 0.f;
        scores[le] = sc;
    }
    __syncthreads();

    {
        int n = tid >> 4, cq = tid & 15;
        float4 a4 = make_float4(0.f, 0.f, 0.f, 0.f);
        #pragma unroll
        for (int k = 0; k < 16; k++) {
            int le = n * 16 + k;
            float sc = scores[le];
            float4 tv = *(const float4*)(tail_emb + (size_t)tlist[le] * 64 + cq * 4);
            a4.x += sc * tv.x; a4.y += sc * tv.y;
            a4.z += sc * tv.z; a4.w += sc * tv.w;
        }
        *(float4*)(g_neigh + (size_t)(d0 + n) * 64 + cq * 4) = a4;
    }
}

// ---------------------------------------------------------------------------
// K4: y = [drug | neigh] @ Wc + bc + column stats.  REWRITTEN:
//   64 rows / 64 threads per block; thread tile 8 rows x 8 cols, FFMA2.
//   A transposed into smem As[j][row], filled in two k-halves (drug, neigh);
//   Wc repacked conflict-free like k_node5's Wp. Per warp per j:
//   16 LDS wavefronts vs 16 SM-fma cycles -> balanced; 32 indep acc chains.
// ---------------------------------------------------------------------------
__global__ __launch_bounds__(64) void k_gemm2(
    const float* __restrict__ drug,
    const float* __restrict__ Wc,
    const float* __restrict__ bc)
{
    extern __shared__ float smg[];
    float* As   = smg;             // [64 j][64 rows]: 16 KB (reused per k-half)
    float* Wp   = smg + 4096;      // repacked Wc [128][64]: 32 KB
    float* rsum = Wp + 8192;       // [8 rg][64]: 2 KB
    float* rsq  = rsum + 512;      // [8 rg][64]: 2 KB
    float* bcs  = rsq + 512;       // 64

    int tid = threadIdx.x;
    int rg = tid >> 3, cg = tid & 7;
    int r0 = blockIdx.x * 64;
    int myrow = r0 + tid;
    bool myvalid = (myrow < ND);

    // Wp fill: Wp[j*64 + half*32 + gg*4 + q] = Wc[j*64 + gg*8 + half*4 + q]
    for (int i = tid; i < 2048; i += 64) {
        int j = i >> 4, t = i & 15;
        int half = t >> 3, gg = t & 7;
        ((float4*)Wp)[j * 16 + half * 8 + gg] =
            ((const float4*)Wc)[j * 16 + gg * 2 + half];
    }
    bcs[tid] = bc[tid];

    // As fill, half 0: drug rows (k = 0..63), transposed
    {
        const float4* src = (const float4*)(drug + (size_t)myrow * 64);
        #pragma unroll 4
        for (int q = 0; q < 16; q++) {
            float4 v = myvalid ? src[q] : make_float4(0.f, 0.f, 0.f, 0.f);
            As[(q * 4 + 0) * 64 + tid] = v.x;
            As[(q * 4 + 1) * 64 + tid] = v.y;
            As[(q * 4 + 2) * 64 + tid] = v.z;
            As[(q * 4 + 3) * 64 + tid] = v.w;
        }
    }
    __syncthreads();

    int c0 = cg * 8;
    unsigned long long acc[8][4];
    {
        ulonglong2 bA = *(const ulonglong2*)(bcs + c0);
        ulonglong2 bB = *(const ulonglong2*)(bcs + c0 + 4);
        #pragma unroll
        for (int e = 0; e < 8; e++) {
            acc[e][0] = bA.x; acc[e][1] = bA.y;
            acc[e][2] = bB.x; acc[e][3] = bB.y;
        }
    }

#define GEMM_J(jbase)                                                          \
    _Pragma("unroll 2")                                                        \
    for (int j = 0; j < 64; j++) {                                             \
        float4 a03 = *(const float4*)(As + j * 64 + rg * 8);                   \
        float4 a47 = *(const float4*)(As + j * 64 + rg * 8 + 4);               \
        const float* wrow = Wp + (j + (jbase)) * 64;                           \
        ulonglong2 wA = *(const ulonglong2*)(wrow + cg * 4);                   \
        ulonglong2 wB = *(const ulonglong2*)(wrow + 32 + cg * 4);              \
        unsigned long long hh;                                                 \
        hh = dup2(a03.x); fma2(acc[0][0],hh,wA.x); fma2(acc[0][1],hh,wA.y); fma2(acc[0][2],hh,wB.x); fma2(acc[0][3],hh,wB.y); \
        hh = dup2(a03.y); fma2(acc[1][0],hh,wA.x); fma2(acc[1][1],hh,wA.y); fma2(acc[1][2],hh,wB.x); fma2(acc[1][3],hh,wB.y); \
        hh = dup2(a03.z); fma2(acc[2][0],hh,wA.x); fma2(acc[2][1],hh,wA.y); fma2(acc[2][2],hh,wB.x); fma2(acc[2][3],hh,wB.y); \
        hh = dup2(a03.w); fma2(acc[3][0],hh,wA.x); fma2(acc[3][1],hh,wA.y); fma2(acc[3][2],hh,wB.x); fma2(acc[3][3],hh,wB.y); \
        hh = dup2(a47.x); fma2(acc[4][0],hh,wA.x); fma2(acc[4][1],hh,wA.y); fma2(acc[4][2],hh,wB.x); fma2(acc[4][3],hh,wB.y); \
        hh = dup2(a47.y); fma2(acc[5][0],hh,wA.x); fma2(acc[5][1],hh,wA.y); fma2(acc[5][2],hh,wB.x); fma2(acc[5][3],hh,wB.y); \
        hh = dup2(a47.z); fma2(acc[6][0],hh,wA.x); fma2(acc[6][1],hh,wA.y); fma2(acc[6][2],hh,wB.x); fma2(acc[6][3],hh,wB.y); \
        hh = dup2(a47.w); fma2(acc[7][0],hh,wA.x); fma2(acc[7][1],hh,wA.y); fma2(acc[7][2],hh,wB.x); fma2(acc[7][3],hh,wB.y); \
    }

    GEMM_J(0)
    __syncthreads();

    // As fill, half 1: neigh rows (k = 64..127)
    {
        const float4* src = (const float4*)(g_neigh + (size_t)myrow * 64);
        #pragma unroll 4
        for (int q = 0; q < 16; q++) {
            float4 v = myvalid ? src[q] : make_float4(0.f, 0.f, 0.f, 0.f);
            As[(q * 4 + 0) * 64 + tid] = v.x;
            As[(q * 4 + 1) * 64 + tid] = v.y;
            As[(q * 4 + 2) * 64 + tid] = v.z;
            As[(q * 4 + 3) * 64 + tid] = v.w;
        }
    }
    __syncthreads();

    GEMM_J(64)
#undef GEMM_J

    // store y + local column stats over this thread's 8 rows
    float ls[8], lq[8];
    #pragma unroll
    for (int i = 0; i < 8; i++) { ls[i] = 0.f; lq[i] = 0.f; }
    #pragma unroll
    for (int e = 0; e < 8; e++) {
        int r = r0 + rg * 8 + e;
        if (r < ND) {
            ulonglong2 lo; lo.x = acc[e][0]; lo.y = acc[e][1];
            ulonglong2 hi; hi.x = acc[e][2]; hi.y = acc[e][3];
            *(ulonglong2*)(g_y + (size_t)r * 64 + c0)     = lo;
            *(ulonglong2*)(g_y + (size_t)r * 64 + c0 + 4) = hi;
            #pragma unroll
            for (int q = 0; q < 4; q++) {
                float2 y = unpack2(acc[e][q]);
                ls[q*2]   += y.x;  lq[q*2]   += y.x * y.x;
                ls[q*2+1] += y.y;  lq[q*2+1] += y.y * y.y;
            }
        }
    }
    #pragma unroll
    for (int i = 0; i < 8; i++) {
        rsum[rg * 64 + c0 + i] = ls[i];
        rsq [rg * 64 + c0 + i] = lq[i];
    }
    __syncthreads();
    {
        int c = tid;                 // 64 threads <-> 64 cols
        float s = 0.f, q = 0.f;
        #pragma unroll
        for (int r = 0; r < 8; r++) { s += rsum[r * 64 + c]; q += rsq[r * 64 + c]; }
        atomicAdd(&g_colsum[c],   s);
        atomicAdd(&g_colsumsq[c], q);
    }
}

// ---------------------------------------------------------------------------
// K5: batchnorm + output (stats recomputed per thread — trivially cheap)
// ---------------------------------------------------------------------------
__global__ void k_out(const float* __restrict__ gamma,
                      const float* __restrict__ beta,
                      float* __restrict__ out)
{
    int i = blockIdx.x * blockDim.x + threadIdx.x;
    if (i < ND * DIM) {
        int k = i & 63;
        float mean = g_colsum[k] * (1.f / ND);
        float var  = g_colsumsq[k] * (1.f / ND) - mean * mean;
        out[i] = gamma[k] * (g_y[i] - mean) * rsqrtf(var + 1e-5f) + beta[k];
    }
}

// ---------------------------------------------------------------------------
// Entry point. Output tuple: [HFEmbeding (10000x64) | out (10000x64) | X (10000)]
// ---------------------------------------------------------------------------
extern "C" void kernel_launch(void* const* d_in, const int* in_sizes, int n_in,
                              void* d_out, int out_size)
{
    const float* HF    = (const float*)d_in[0];
    const float* X     = (const float*)d_in[1];
    const float* drug  = (const float*)d_in[2];
    const float* rel   = (const float*)d_in[3];
    const float* tail  = (const float*)d_in[4];
    const float* W1    = (const float*)d_in[5];
    const float* b1    = (const float*)d_in[6];
    const float* W2    = (const float*)d_in[7];
    const float* b2    = (const float*)d_in[8];
    const float* Wc    = (const float*)d_in[9];
    const float* bc    = (const float*)d_in[10];
    const float* gamma = (const float*)d_in[11];
    const float* beta  = (const float*)d_in[12];
    const int*   DKG   = (const int*)d_in[13];
    float* out = (float*)d_out;

    const int node_smem = (8192 + 4096 + 512 + 64 + 64 + 128) * 4 + 384 * 4;
    const int gemm_smem = (4096 + 8192 + 512 + 512 + 64) * 4;   // 53504 B
    cudaFuncSetAttribute(k_node5, cudaFuncAttributeMaxDynamicSharedMemorySize,
                         node_smem);
    cudaFuncSetAttribute(k_gemm2, cudaFuncAttributeMaxDynamicSharedMemorySize,
                         gemm_smem);

    k_scatter <<<(E + 255) / 256, 256>>>(DKG);
    k_select2 <<<ND / 8, 256>>>(W2, b2);
    k_node5   <<<ND / 8, 128, node_smem>>>(DKG, drug, rel, tail, W1, b1);
    k_gemm2   <<<(ND + 63) / 64, 64, gemm_smem>>>(drug, Wc, bc);
    k_out     <<<(ND * DIM + 255) / 256, 256>>>(gamma, beta, out + ND * DIM);

    cudaMemcpyAsync(out,                HF, (size_t)ND * DIM * sizeof(float),
                    cudaMemcpyDeviceToDevice);
    cudaMemcpyAsync(out + 2 * ND * DIM, X,  (size_t)ND * sizeof(float),
                    cudaMemcpyDeviceToDevice);
}

// round 15
// speedup vs baseline: 1.5857x; 1.0187x over previous
#include <cuda_runtime.h>
#include <cstdint>
#include <cstddef>

// ---------------------------------------------------------------------------
// Problem constants
// ---------------------------------------------------------------------------
#define JAX_PARTITIONABLE 1   // modern JAX default (threefry_partitionable=True)

constexpr int ND  = 10000;    // N_DRUGS
constexpr int E   = 1000000;
constexpr int DIM = 64;
constexpr int S   = 16;       // SAMPLE_SIZE
constexpr int CAP = 192;      // per-node bucket capacity (max deg ~150 here)

// ---------------------------------------------------------------------------
// Static device scratch (no runtime allocation allowed)
// ---------------------------------------------------------------------------
__device__ unsigned long long g_bucket[(size_t)ND * CAP];  // (m<<20)|edge_idx
__device__ int   g_cnt[ND];
__device__ int   g_sel[ND * S];      // ALL 16 slots valid after select (-1 if none)
__device__ float g_neigh[ND * DIM];
__device__ float g_y[ND * DIM];
__device__ float g_colsum[DIM];
__device__ float g_colsumsq[DIM];
__device__ float g_w2r[DIM];         // rowsum of W2
__device__ float g_b2sum;

// ---------------------------------------------------------------------------
// Threefry2x32 (bit-exact JAX replica)
// ---------------------------------------------------------------------------
__device__ __forceinline__ uint32_t rotl32(uint32_t v, int r) {
    return (v << r) | (v >> (32 - r));
}

__device__ __forceinline__ void tf2x32(uint32_t k0, uint32_t k1,
                                       uint32_t x0, uint32_t x1,
                                       uint32_t& o0, uint32_t& o1)
{
    uint32_t k2 = k0 ^ k1 ^ 0x1BD11BDAu;
    x0 += k0; x1 += k1;
#define TF_R4(a,b,c,d)                                   \
    x0 += x1; x1 = rotl32(x1,a); x1 ^= x0;               \
    x0 += x1; x1 = rotl32(x1,b); x1 ^= x0;               \
    x0 += x1; x1 = rotl32(x1,c); x1 ^= x0;               \
    x0 += x1; x1 = rotl32(x1,d); x1 ^= x0;
    TF_R4(13,15,26,6);   x0 += k1; x1 += k2 + 1u;
    TF_R4(17,29,16,24);  x0 += k2; x1 += k0 + 2u;
    TF_R4(13,15,26,6);   x0 += k0; x1 += k1 + 3u;
    TF_R4(17,29,16,24);  x0 += k1; x1 += k2 + 4u;
    TF_R4(13,15,26,6);   x0 += k2; x1 += k0 + 5u;
#undef TF_R4
    o0 = x0; o1 = x1;
}

__device__ __forceinline__ void derive_k1(uint32_t& a, uint32_t& b) {
#if JAX_PARTITIONABLE
    tf2x32(0u, 42u, 0u, 0u, a, b);
#else
    uint32_t a0,b0,a1,b1;
    tf2x32(0u, 42u, 0u, 2u, a0, b0);
    tf2x32(0u, 42u, 1u, 3u, a1, b1);
    a = a0; b = a1;
#endif
}

__device__ __forceinline__ void derive_k2(uint32_t& a, uint32_t& b) {
#if JAX_PARTITIONABLE
    tf2x32(0u, 42u, 0u, 1u, a, b);
#else
    uint32_t a0,b0,a1,b1;
    tf2x32(0u, 42u, 0u, 2u, a0, b0);
    tf2x32(0u, 42u, 1u, 3u, a1, b1);
    a = b0; b = b1;
#endif
}

__device__ __forceinline__ uint32_t jax_bits32(uint32_t ka, uint32_t kb,
                                               uint32_t i, uint32_t n)
{
#if JAX_PARTITIONABLE
    uint32_t o0, o1;
    tf2x32(ka, kb, 0u, i, o0, o1);
    return o0 ^ o1;
#else
    uint32_t half = n >> 1;
    uint32_t j = (i < half) ? i : (i - half);
    uint32_t o0, o1;
    tf2x32(ka, kb, j, j + half, o0, o1);
    return (i < half) ? o0 : o1;
#endif
}

// ---------------------------------------------------------------------------
// Packed fp32x2 helpers (FFMA2 path — only reachable via PTX)
// ---------------------------------------------------------------------------
__device__ __forceinline__ void fma2(unsigned long long& acc,
                                     unsigned long long a,
                                     unsigned long long b)
{
    asm("fma.rn.f32x2 %0, %1, %2, %0;" : "+l"(acc) : "l"(a), "l"(b));
}
__device__ __forceinline__ unsigned long long dup2(float v)
{
    unsigned long long r;
    asm("mov.b64 %0, {%1, %1};" : "=l"(r) : "f"(v));
    return r;
}
__device__ __forceinline__ float2 unpack2(unsigned long long u)
{
    union { unsigned long long u; float2 f; } cv;
    cv.u = u;
    return cv.f;
}

// ---------------------------------------------------------------------------
// K1: per-edge uniform r, scatter (m<<20 | edge_idx) into per-node buckets
// ---------------------------------------------------------------------------
__global__ void k_scatter(const int* __restrict__ DKG)
{
    int i = blockIdx.x * blockDim.x + threadIdx.x;
    if (i >= E) return;
    uint32_t ka, kb;
    derive_k1(ka, kb);
    uint32_t bits = jax_bits32(ka, kb, (uint32_t)i, (uint32_t)E);
    uint32_t m = bits >> 9;                   // r = m * 2^-23 exactly
    int head = __ldg(&DKG[3 * i]);
    int c = atomicAdd(&g_cnt[head], 1);
    if (c < CAP)
        g_bucket[(size_t)head * CAP + c] =
            (((unsigned long long)m) << 20) | (unsigned long long)(uint32_t)i;
}

// ---------------------------------------------------------------------------
// K2: warp-per-node iterative extract-min (exact stable ranks 0..15).
//   Also clears g_cnt for the next replay; block 0 does the old k_init work.
// ---------------------------------------------------------------------------
__global__ __launch_bounds__(256) void k_select2(
    const float* __restrict__ W2, const float* __restrict__ b2)
{
    int lane = threadIdx.x & 31;
    int d = blockIdx.x * 8 + (threadIdx.x >> 5);
    int deg = g_cnt[d]; if (deg > CAP) deg = CAP;
    if (lane == 0) g_cnt[d] = 0;               // reset for next graph replay

    unsigned long long ku[6];
    #pragma unroll
    for (int s = 0; s < 6; s++) {
        int i = lane + 32 * s;
        ku[s] = (i < deg) ? g_bucket[(size_t)d * CAP + i] : ~0ull;
    }
    int nsel = (deg < S) ? deg : S;
    int myE = -1;                              // lane 'sel' keeps rank-sel edge
    for (int sel = 0; sel < S; sel++) {
        unsigned long long m = ku[0];
        #pragma unroll
        for (int s = 1; s < 6; s++) m = (ku[s] < m) ? ku[s] : m;
        #pragma unroll
        for (int o = 16; o; o >>= 1) {
            unsigned long long oth = __shfl_xor_sync(0xFFFFFFFFu, m, o);
            m = (oth < m) ? oth : m;
        }
        #pragma unroll
        for (int s = 0; s < 6; s++) if (ku[s] == m) ku[s] = ~0ull;
        if (lane == sel) myE = (m == ~0ull) ? -1 : (int)(m & 0xFFFFFull);
    }

    int e2 = myE;
    if (nsel < S && deg > 0) {                 // uniform per warp; dead in practice
        uint32_t ka, kb; derive_k2(ka, kb);
        uint32_t idx = (uint32_t)(d * S + (lane - nsel));
        uint32_t hi = jax_bits32(ka, kb, idx,          2u * ND * S);
        uint32_t lo = jax_bits32(ka, kb, idx + ND * S, 2u * ND * S);
        const uint32_t span = 2147483647u;
        uint32_t mult = (65536u * 65536u) % span;
        uint32_t off  = ((hi % span) * mult + (lo % span)) % span;
        bool need = (lane >= nsel) && (lane < S);
        int src = need ? (int)(off % (uint32_t)deg) : lane;
        int v = __shfl_sync(0xFFFFFFFFu, myE, src);
        if (need) e2 = v;
    }
    if (lane < S) g_sel[d * S + lane] = e2;

    // ---- block 0 extras (old k_init) ----
    if (blockIdx.x == 0) {
        int t = threadIdx.x;
        if (t < DIM) {
            g_colsum[t]   = 0.f;
            g_colsumsq[t] = 0.f;
            float s = 0.f;
            #pragma unroll 8
            for (int k = 0; k < DIM; k++) s += W2[t * DIM + k];
            g_w2r[t] = s;
        }
        if (t == 64) {
            float s = 0.f;
            #pragma unroll 8
            for (int k = 0; k < DIM; k++) s += b2[k];
            g_b2sum = s;
        }
    }
}

// ---------------------------------------------------------------------------
// K3: 8 nodes / block, 128 edges / block, 128 threads (unchanged from R12).
// ---------------------------------------------------------------------------
__global__ __launch_bounds__(128, 4) void k_node5(
    const int*   __restrict__ DKG,
    const float* __restrict__ drug,
    const float* __restrict__ rel_emb,
    const float* __restrict__ tail_emb,
    const float* __restrict__ W1,
    const float* __restrict__ b1)
{
    extern __shared__ float sm[];
    float* Hs     = sm;                    // [64 j][128 edges]: 32 KB
    float* Wp     = sm + 8192;             // repacked W1 [j][64]: 16 KB
    float* de     = Wp + 4096;             // [8 nodes][64]: 2 KB
    float* b1s    = de + 512;              // 64
    float* w2s    = b1s + 64;              // 64
    float* scores = w2s + 64;              // 128
    int*   elist  = (int*)(scores + 128);  // 128
    int*   tlist  = elist + 128;           // 128
    int*   rlist  = tlist + 128;           // 128

    int tid  = threadIdx.x;
    int lane = tid & 31, w = tid >> 5;
    int g    = lane & 7, eg = lane >> 3;
    int d0   = blockIdx.x * 8;

    for (int i = tid; i < 1024; i += 128) {
        int j = i >> 4, t = i & 15;
        int half = t >> 3, gg = t & 7;
        ((float4*)Wp)[j * 16 + half * 8 + gg] =
            ((const float4*)W1)[j * 16 + gg * 2 + half];
    }
    if (tid < 64) { b1s[tid] = b1[tid]; w2s[tid] = g_w2r[tid]; }
    {
        int n = tid >> 4, q = tid & 15;
        ((float4*)de)[tid] = ((const float4*)(drug + (size_t)(d0 + n) * 64))[q];
        int e = g_sel[(d0 + n) * S + q];
        elist[tid] = e;
        int ee = (e < 0) ? 0 : e;
        tlist[tid] = DKG[3 * ee + 1];
        rlist[tid] = DKG[3 * ee + 2];
    }
    __syncthreads();

    {
        int le = tid;
        int n  = le >> 4;
        const float4* rr = (const float4*)(rel_emb + (size_t)rlist[le] * 64);
        const float4* dn = (const float4*)(de + n * 64);
        #pragma unroll
        for (int jq = 0; jq < 16; jq++) {
            float4 rv = rr[jq], dv = dn[jq];
            int j = jq * 4;
            Hs[(j + 0) * 128 + le] = dv.x * rv.x;
            Hs[(j + 1) * 128 + le] = dv.y * rv.y;
            Hs[(j + 2) * 128 + le] = dv.z * rv.z;
            Hs[(j + 3) * 128 + le] = dv.w * rv.w;
        }
    }
    __syncthreads();

    int e0 = w * 32 + eg * 8;   // thread's 8 edges
    int c0 = g * 8;             // thread's 8 cols (logical)

    unsigned long long acc[8][4];
    {
        ulonglong2 bA = *(const ulonglong2*)(b1s + c0);
        ulonglong2 bB = *(const ulonglong2*)(b1s + c0 + 4);
        #pragma unroll
        for (int e = 0; e < 8; e++) {
            acc[e][0] = bA.x; acc[e][1] = bA.y;
            acc[e][2] = bB.x; acc[e][3] = bB.y;
        }
    }

    #pragma unroll 2
    for (int j = 0; j < 64; j++) {
        float4 h03 = *(const float4*)(Hs + j * 128 + e0);
        float4 h47 = *(const float4*)(Hs + j * 128 + e0 + 4);
        ulonglong2 wA = *(const ulonglong2*)(Wp + j * 64 + g * 4);
        ulonglong2 wB = *(const ulonglong2*)(Wp + j * 64 + 32 + g * 4);
        unsigned long long hh;
        hh = dup2(h03.x); fma2(acc[0][0],hh,wA.x); fma2(acc[0][1],hh,wA.y); fma2(acc[0][2],hh,wB.x); fma2(acc[0][3],hh,wB.y);
        hh = dup2(h03.y); fma2(acc[1][0],hh,wA.x); fma2(acc[1][1],hh,wA.y); fma2(acc[1][2],hh,wB.x); fma2(acc[1][3],hh,wB.y);
        hh = dup2(h03.z); fma2(acc[2][0],hh,wA.x); fma2(acc[2][1],hh,wA.y); fma2(acc[2][2],hh,wB.x); fma2(acc[2][3],hh,wB.y);
        hh = dup2(h03.w); fma2(acc[3][0],hh,wA.x); fma2(acc[3][1],hh,wA.y); fma2(acc[3][2],hh,wB.x); fma2(acc[3][3],hh,wB.y);
        hh = dup2(h47.x); fma2(acc[4][0],hh,wA.x); fma2(acc[4][1],hh,wA.y); fma2(acc[4][2],hh,wB.x); fma2(acc[4][3],hh,wB.y);
        hh = dup2(h47.y); fma2(acc[5][0],hh,wA.x); fma2(acc[5][1],hh,wA.y); fma2(acc[5][2],hh,wB.x); fma2(acc[5][3],hh,wB.y);
        hh = dup2(h47.z); fma2(acc[6][0],hh,wA.x); fma2(acc[6][1],hh,wA.y); fma2(acc[6][2],hh,wB.x); fma2(acc[6][3],hh,wB.y);
        hh = dup2(h47.w); fma2(acc[7][0],hh,wA.x); fma2(acc[7][1],hh,wA.y); fma2(acc[7][2],hh,wB.x); fma2(acc[7][3],hh,wB.y);
    }

    float2 w2q[4];
    {
        float4 wa = *(const float4*)(w2s + c0);
        float4 wb = *(const float4*)(w2s + c0 + 4);
        w2q[0] = make_float2(wa.x, wa.y); w2q[1] = make_float2(wa.z, wa.w);
        w2q[2] = make_float2(wb.x, wb.y); w2q[3] = make_float2(wb.z, wb.w);
    }
    float p[8];
    #pragma unroll
    for (int e = 0; e < 8; e++) {
        float s = 0.f;
        #pragma unroll
        for (int q = 0; q < 4; q++) {
            float2 y = unpack2(acc[e][q]);
            s += w2q[q].x * __fdividef(1.f, 1.f + __expf(-y.x));
            s += w2q[q].y * __fdividef(1.f, 1.f + __expf(-y.y));
        }
        p[e] = s;
    }
    #pragma unroll
    for (int o = 1; o < 8; o <<= 1) {
        #pragma unroll
        for (int e = 0; e < 8; e++)
            p[e] += __shfl_xor_sync(0xFFFFFFFFu, p[e], o);
    }
    {
        float mysum = p[0];
        #pragma unroll
        for (int e = 1; e < 8; e++) if (g == e) mysum = p[e];
        int le = e0 + g;
        float sc = (elist[le] >= 0) ? (mysum + g_b2sum) : 0.f;
        scores[le] = sc;
    }
    __syncthreads();

    {
        int n = tid >> 4, cq = tid & 15;
        float4 a4 = make_float4(0.f, 0.f, 0.f, 0.f);
        #pragma unroll
        for (int k = 0; k < 16; k++) {
            int le = n * 16 + k;
            float sc = scores[le];
            float4 tv = *(const float4*)(tail_emb + (size_t)tlist[le] * 64 + cq * 4);
            a4.x += sc * tv.x; a4.y += sc * tv.y;
            a4.z += sc * tv.z; a4.w += sc * tv.w;
        }
        *(float4*)(g_neigh + (size_t)(d0 + n) * 64 + cq * 4) = a4;
    }
}

// ---------------------------------------------------------------------------
// K4: y = [drug | neigh] @ Wc + bc + column stats.  REWRITE of R13's k_gemm2:
//   still 64 rows/block but 128 threads (4 warps -> all 4 SMSPs issue).
//   Thread tile 4 rows x 8 cols (16 FFMA2/j). Per warp per j: A 1xLDS.128
//   (4 wf) + W 2xLDS.128 conflict-free (8 wf) = 12 wf vs 16 FFMA2.
//   Fills are split: threads 0-63 load As rows, threads 64-127 repack Wc.
// ---------------------------------------------------------------------------
__global__ __launch_bounds__(128) void k_gemm3(
    const float* __restrict__ drug,
    const float* __restrict__ Wc,
    const float* __restrict__ bc)
{
    extern __shared__ float smg[];
    float* As   = smg;             // [64 j][64 rows]: 16 KB (reused per k-half)
    float* Wp   = smg + 4096;      // repacked Wc [128][64]: 32 KB
    float* rsum = Wp + 8192;       // [16 rg][64]: 4 KB
    float* rsq  = rsum + 1024;     // 4 KB
    float* bcs  = rsq + 1024;      // 64

    int tid = threadIdx.x;
    int rg = tid >> 3, cg = tid & 7;   // 16 row-groups x 8 col-groups
    int r0 = blockIdx.x * 64;

    // parallel fills: low half -> As (drug k-half) + bcs; high half -> Wp
    if (tid < 64) {
        int row = r0 + tid;
        bool v = (row < ND);
        const float4* src = (const float4*)(drug + (size_t)row * 64);
        #pragma unroll 4
        for (int q = 0; q < 16; q++) {
            float4 val = v ? src[q] : make_float4(0.f, 0.f, 0.f, 0.f);
            As[(q * 4 + 0) * 64 + tid] = val.x;
            As[(q * 4 + 1) * 64 + tid] = val.y;
            As[(q * 4 + 2) * 64 + tid] = val.z;
            As[(q * 4 + 3) * 64 + tid] = val.w;
        }
        bcs[tid] = bc[tid];
    } else {
        // Wp fill: Wp[j*16 + half*8 + gg] (f4) = Wc[j*16 + gg*2 + half] (f4)
        for (int i = tid - 64; i < 2048; i += 64) {
            int j = i >> 4, t = i & 15;
            int half = t >> 3, gg = t & 7;
            ((float4*)Wp)[j * 16 + half * 8 + gg] =
                ((const float4*)Wc)[j * 16 + gg * 2 + half];
        }
    }
    __syncthreads();

    int c0 = cg * 8;
    unsigned long long acc[4][4];      // [row][col-pair]
    {
        ulonglong2 bA = *(const ulonglong2*)(bcs + c0);
        ulonglong2 bB = *(const ulonglong2*)(bcs + c0 + 4);
        #pragma unroll
        for (int r = 0; r < 4; r++) {
            acc[r][0] = bA.x; acc[r][1] = bA.y;
            acc[r][2] = bB.x; acc[r][3] = bB.y;
        }
    }

#define GEMM_J(jbase)                                                          \
    _Pragma("unroll 4")                                                        \
    for (int j = 0; j < 64; j++) {                                             \
        float4 av = *(const float4*)(As + j * 64 + rg * 4);                    \
        const float* wrow = Wp + (j + (jbase)) * 64;                           \
        ulonglong2 wA = *(const ulonglong2*)(wrow + cg * 4);                   \
        ulonglong2 wB = *(const ulonglong2*)(wrow + 32 + cg * 4);              \
        unsigned long long hh;                                                 \
        hh = dup2(av.x); fma2(acc[0][0],hh,wA.x); fma2(acc[0][1],hh,wA.y); fma2(acc[0][2],hh,wB.x); fma2(acc[0][3],hh,wB.y); \
        hh = dup2(av.y); fma2(acc[1][0],hh,wA.x); fma2(acc[1][1],hh,wA.y); fma2(acc[1][2],hh,wB.x); fma2(acc[1][3],hh,wB.y); \
        hh = dup2(av.z); fma2(acc[2][0],hh,wA.x); fma2(acc[2][1],hh,wA.y); fma2(acc[2][2],hh,wB.x); fma2(acc[2][3],hh,wB.y); \
        hh = dup2(av.w); fma2(acc[3][0],hh,wA.x); fma2(acc[3][1],hh,wA.y); fma2(acc[3][2],hh,wB.x); fma2(acc[3][3],hh,wB.y); \
    }

    GEMM_J(0)
    __syncthreads();

    // As refill: neigh k-half
    if (tid < 64) {
        int row = r0 + tid;
        bool v = (row < ND);
        const float4* src = (const float4*)(g_neigh + (size_t)row * 64);
        #pragma unroll 4
        for (int q = 0; q < 16; q++) {
            float4 val = v ? src[q] : make_float4(0.f, 0.f, 0.f, 0.f);
            As[(q * 4 + 0) * 64 + tid] = val.x;
            As[(q * 4 + 1) * 64 + tid] = val.y;
            As[(q * 4 + 2) * 64 + tid] = val.z;
            As[(q * 4 + 3) * 64 + tid] = val.w;
        }
    }
    __syncthreads();

    GEMM_J(64)
#undef GEMM_J

    // store y + local column stats over this thread's 4 rows
    float ls[8], lq[8];
    #pragma unroll
    for (int i = 0; i < 8; i++) { ls[i] = 0.f; lq[i] = 0.f; }
    #pragma unroll
    for (int r = 0; r < 4; r++) {
        int row = r0 + rg * 4 + r;
        if (row < ND) {
            ulonglong2 lo; lo.x = acc[r][0]; lo.y = acc[r][1];
            ulonglong2 hi; hi.x = acc[r][2]; hi.y = acc[r][3];
            *(ulonglong2*)(g_y + (size_t)row * 64 + c0)     = lo;
            *(ulonglong2*)(g_y + (size_t)row * 64 + c0 + 4) = hi;
            #pragma unroll
            for (int q = 0; q < 4; q++) {
                float2 y = unpack2(acc[r][q]);
                ls[q*2]   += y.x;  lq[q*2]   += y.x * y.x;
                ls[q*2+1] += y.y;  lq[q*2+1] += y.y * y.y;
            }
        }
    }
    #pragma unroll
    for (int i = 0; i < 8; i++) {
        rsum[rg * 64 + c0 + i] = ls[i];
        rsq [rg * 64 + c0 + i] = lq[i];
    }
    __syncthreads();
    if (tid < 64) {
        int c = tid;                 // 64 threads <-> 64 cols
        float s = 0.f, q = 0.f;
        #pragma unroll
        for (int r = 0; r < 16; r++) { s += rsum[r * 64 + c]; q += rsq[r * 64 + c]; }
        atomicAdd(&g_colsum[c],   s);
        atomicAdd(&g_colsumsq[c], q);
    }
}

// ---------------------------------------------------------------------------
// K5: batchnorm + output (stats recomputed per thread — trivially cheap)
// ---------------------------------------------------------------------------
__global__ void k_out(const float* __restrict__ gamma,
                      const float* __restrict__ beta,
                      float* __restrict__ out)
{
    int i = blockIdx.x * blockDim.x + threadIdx.x;
    if (i < ND * DIM) {
        int k = i & 63;
        float mean = g_colsum[k] * (1.f / ND);
        float var  = g_colsumsq[k] * (1.f / ND) - mean * mean;
        out[i] = gamma[k] * (g_y[i] - mean) * rsqrtf(var + 1e-5f) + beta[k];
    }
}

// ---------------------------------------------------------------------------
// Entry point. Output tuple: [HFEmbeding (10000x64) | out (10000x64) | X (10000)]
// ---------------------------------------------------------------------------
extern "C" void kernel_launch(void* const* d_in, const int* in_sizes, int n_in,
                              void* d_out, int out_size)
{
    const float* HF    = (const float*)d_in[0];
    const float* X     = (const float*)d_in[1];
    const float* drug  = (const float*)d_in[2];
    const float* rel   = (const float*)d_in[3];
    const float* tail  = (const float*)d_in[4];
    const float* W1    = (const float*)d_in[5];
    const float* b1    = (const float*)d_in[6];
    const float* W2    = (const float*)d_in[7];
    const float* b2    = (const float*)d_in[8];
    const float* Wc    = (const float*)d_in[9];
    const float* bc    = (const float*)d_in[10];
    const float* gamma = (const float*)d_in[11];
    const float* beta  = (const float*)d_in[12];
    const int*   DKG   = (const int*)d_in[13];
    float* out = (float*)d_out;

    const int node_smem = (8192 + 4096 + 512 + 64 + 64 + 128) * 4 + 384 * 4;
    const int gemm_smem = (4096 + 8192 + 1024 + 1024 + 64) * 4;   // 57632 B
    cudaFuncSetAttribute(k_node5, cudaFuncAttributeMaxDynamicSharedMemorySize,
                         node_smem);
    cudaFuncSetAttribute(k_gemm3, cudaFuncAttributeMaxDynamicSharedMemorySize,
                         gemm_smem);

    k_scatter <<<(E + 255) / 256, 256>>>(DKG);
    k_select2 <<<ND / 8, 256>>>(W2, b2);
    k_node5   <<<ND / 8, 128, node_smem>>>(DKG, drug, rel, tail, W1, b1);
    k_gemm3   <<<(ND + 63) / 64, 128, gemm_smem>>>(drug, Wc, bc);
    k_out     <<<(ND * DIM + 255) / 256, 256>>>(gamma, beta, out + ND * DIM);

    cudaMemcpyAsync(out,                HF, (size_t)ND * DIM * sizeof(float),
                    cudaMemcpyDeviceToDevice);
    cudaMemcpyAsync(out + 2 * ND * DIM, X,  (size_t)ND * sizeof(float),
                    cudaMemcpyDeviceToDevice);
}